// round 11
// baseline (speedup 1.0000x reference)
#include <cuda_runtime.h>
#include <math.h>
#include <stdint.h>

// Problem constants
#define BB 4
#define SS 2048
#define HH 16
#define DH 64
#define DD 1024            // H*DH
#define ROWS (BB*SS)       // 8192
#define N_QKV (3*DD)       // 3072
#define FF_IN 4096
#define FF_HID 2048

// Scratch (device globals; no allocation)
__device__ float g_qkv [(size_t)ROWS * N_QKV];   // [B*S, 3072]
__device__ float g_aq  [(size_t)ROWS * DD];      // tf32-rounded q
__device__ float g_q   [(size_t)ROWS * DD];      // [B*H, S, 64] tf32, pre-scaled 0.125
__device__ float g_k   [(size_t)ROWS * DD];      // [B*H, S, 64] tf32
__device__ float g_v   [(size_t)ROWS * DD];      // [B*H, S, 64] raw
__device__ float g_vT  [(size_t)ROWS * DD];      // [B*H, 64, S] tf32
__device__ float g_attn[(size_t)ROWS * DD];      // [B*S, 1024]
__device__ float g_ln  [(size_t)ROWS * DD];      // LN out (fp32, residual)
__device__ float g_lnr [(size_t)ROWS * DD];      // LN out tf32-rounded (GEMM A)
__device__ float g_gate[(size_t)ROWS * FF_HID];  // [B*S, 2048] tf32-rounded
__device__ float g_wqkvT[(size_t)N_QKV * DD];    // [3072, 1024]
__device__ float g_w1T  [(size_t)FF_IN * DD];    // [4096, 1024] x/gate interleaved
__device__ float g_w2T  [(size_t)DD * FF_HID];   // [1024, 2048]
__device__ float g_pb1  [FF_IN];                 // permuted b1

// ---------------------------------------------------------------------------
// helpers
// ---------------------------------------------------------------------------
__device__ __forceinline__ float tf32r(float x) {
    float o; asm("cvt.rna.tf32.f32 %0, %1;" : "=f"(o) : "f"(x)); return o;
}
__device__ __forceinline__ uint32_t smem_u32(const void* p) {
    uint32_t a;
    asm("{ .reg .u64 t; cvta.to.shared.u64 t, %1; cvt.u32.u64 %0, t; }" : "=r"(a) : "l"(p));
    return a;
}
__device__ __forceinline__ void cpasync16(uint32_t dst, const void* src) {
    asm volatile("cp.async.cg.shared.global [%0], [%1], 16;" :: "r"(dst), "l"(src) : "memory");
}
__device__ __forceinline__ void cp_commit() {
    asm volatile("cp.async.commit_group;" ::: "memory");
}
__device__ __forceinline__ void cp_wait1() {
    asm volatile("cp.async.wait_group 1;" ::: "memory");
}
__device__ __forceinline__ void cp_wait0() {
    asm volatile("cp.async.wait_group 0;" ::: "memory");
}
__device__ __forceinline__ void mma_tf32(float* c, const uint32_t* a, const uint32_t* b) {
    asm volatile(
        "mma.sync.aligned.m16n8k8.row.col.f32.tf32.tf32.f32 "
        "{%0,%1,%2,%3}, {%4,%5,%6,%7}, {%8,%9}, {%0,%1,%2,%3};"
        : "+f"(c[0]), "+f"(c[1]), "+f"(c[2]), "+f"(c[3])
        : "r"(a[0]), "r"(a[1]), "r"(a[2]), "r"(a[3]), "r"(b[0]), "r"(b[1]));
}

// ---------------------------------------------------------------------------
// tf32 mma.sync GEMM: C[M,N] = A[M,K] @ Bt[N,K]^T + bias (+ res)
// SWIGLU=true: N cols are (x,gate) interleaved pairs; writes silu(g)*x to
// C[M, N/2] (tf32-rounded), res unused.
// ---------------------------------------------------------------------------
#define GBM 128
#define GBN 128
#define GBK 32
#define APAD 36
#define STAGE_F (2 * 128 * APAD)   // floats per stage (A+B)

template<bool SWIGLU>
__global__ __launch_bounds__(256) void gemm_mma_kernel(
    const float* __restrict__ A, const float* __restrict__ Bt,
    const float* __restrict__ bias, const float* __restrict__ res,
    float* __restrict__ C, int N, int K)
{
    extern __shared__ float sm[];
    const int tid = threadIdx.x;
    const int wid = tid >> 5, lane = tid & 31;
    const int g = lane >> 2, tg = lane & 3;
    const int warp_m = wid & 3, warp_n = wid >> 2;
    const int m0 = blockIdx.y * GBM, n0 = blockIdx.x * GBN;
    const uint32_t smbase = smem_u32(sm);

    float acc[2][8][4] = {};

    const int NIT = K >> 5;

    auto load_stage = [&](int it, int s) {
        const int k0 = it * GBK;
        const uint32_t aB = smbase + (uint32_t)s * STAGE_F * 4;
        const uint32_t bB = aB + 128 * APAD * 4;
#pragma unroll
        for (int i = 0; i < 4; i++) {
            const int idx = tid + 256 * i;
            const int row = idx >> 3, c4 = (idx & 7) * 4;
            cpasync16(aB + (uint32_t)(row * APAD + c4) * 4,
                      A  + (size_t)(m0 + row) * K + k0 + c4);
            cpasync16(bB + (uint32_t)(row * APAD + c4) * 4,
                      Bt + (size_t)(n0 + row) * K + k0 + c4);
        }
        cp_commit();
    };

    load_stage(0, 0);

    for (int it = 0; it < NIT; it++) {
        const int s = it & 1;
        if (it + 1 < NIT) load_stage(it + 1, s ^ 1);
        if (it + 1 < NIT) cp_wait1(); else cp_wait0();
        __syncthreads();

        const uint32_t* Asm = (const uint32_t*)(sm + s * STAGE_F);
        const uint32_t* Bsm = Asm + 128 * APAD;

#pragma unroll
        for (int kt = 0; kt < 4; kt++) {
            const int k = kt * 8;
            uint32_t a[2][4], b[8][2];
#pragma unroll
            for (int mi = 0; mi < 2; mi++) {
                const uint32_t* ap = Asm + (warp_m * 32 + mi * 16 + g) * APAD + k + tg;
                a[mi][0] = ap[0];
                a[mi][1] = ap[8 * APAD];
                a[mi][2] = ap[4];
                a[mi][3] = ap[8 * APAD + 4];
            }
#pragma unroll
            for (int ni = 0; ni < 8; ni++) {
                const uint32_t* bp = Bsm + (warp_n * 64 + ni * 8 + g) * APAD + k + tg;
                b[ni][0] = bp[0];
                b[ni][1] = bp[4];
            }
#pragma unroll
            for (int mi = 0; mi < 2; mi++)
#pragma unroll
                for (int ni = 0; ni < 8; ni++)
                    mma_tf32(acc[mi][ni], a[mi], b[ni]);
        }
        __syncthreads();
    }

    if (SWIGLU) {
        // cols (even, odd) = (x, gate) pair; write silu(gate)*x to C[M, N/2]
        const int NH = N >> 1;
#pragma unroll
        for (int mi = 0; mi < 2; mi++) {
            const int row0 = m0 + warp_m * 32 + mi * 16 + g;
#pragma unroll
            for (int ni = 0; ni < 8; ni++) {
                const int col = n0 + warp_n * 64 + ni * 8 + tg * 2;
                const float2 bv = *(const float2*)(bias + col);
                const float x0 = acc[mi][ni][0] + bv.x;
                const float g0 = acc[mi][ni][1] + bv.y;
                const float x1 = acc[mi][ni][2] + bv.x;
                const float g1 = acc[mi][ni][3] + bv.y;
                const float o0 = tf32r(x0 * g0 / (1.0f + __expf(-g0)));
                const float o1 = tf32r(x1 * g1 / (1.0f + __expf(-g1)));
                C[(size_t)row0 * NH + (col >> 1)] = o0;
                C[(size_t)(row0 + 8) * NH + (col >> 1)] = o1;
            }
        }
    } else {
#pragma unroll
        for (int mi = 0; mi < 2; mi++) {
            const int row0 = m0 + warp_m * 32 + mi * 16 + g;
#pragma unroll
            for (int ni = 0; ni < 8; ni++) {
                const int col = n0 + warp_n * 64 + ni * 8 + tg * 2;
                const float2 bv = *(const float2*)(bias + col);
                float2 o0, o1;
                o0.x = acc[mi][ni][0] + bv.x;
                o0.y = acc[mi][ni][1] + bv.y;
                o1.x = acc[mi][ni][2] + bv.x;
                o1.y = acc[mi][ni][3] + bv.y;
                if (res) {
                    const float2 r0 = *(const float2*)(res + (size_t)row0 * N + col);
                    const float2 r1 = *(const float2*)(res + (size_t)(row0 + 8) * N + col);
                    o0.x += r0.x; o0.y += r0.y; o1.x += r1.x; o1.y += r1.y;
                }
                *(float2*)(C + (size_t)row0 * N + col) = o0;
                *(float2*)(C + (size_t)(row0 + 8) * N + col) = o1;
            }
        }
    }
}

// ---------------------------------------------------------------------------
// Transpose + tf32-round: out[c*R + r] = rnd(in[r*Cc + c])
// PERM=1: output row index remapped for x/gate interleave (Cc=4096 case):
//         new_row = r<2048 ? 2r : 2(r-2048)+1
// ---------------------------------------------------------------------------
template<int PERM>
__global__ __launch_bounds__(256) void transpose_round_kernel(
    const float* __restrict__ in, float* __restrict__ out, int R, int Cc)
{
    __shared__ float t[32][33];
    const int bx = blockIdx.x, by = blockIdx.y;
    const int tx = threadIdx.x, ty = threadIdx.y;
#pragma unroll
    for (int i = 0; i < 32; i += 8)
        t[ty + i][tx] = in[(size_t)(by * 32 + ty + i) * Cc + bx * 32 + tx];
    __syncthreads();
#pragma unroll
    for (int i = 0; i < 32; i += 8) {
        int r = bx * 32 + ty + i;
        if (PERM) r = (r < 2048) ? (2 * r) : (2 * (r - 2048) + 1);
        out[(size_t)r * R + by * 32 + tx] = tf32r(t[tx][ty + i]);
    }
}

// Batched V transpose per head: g_v [bh][s][d] -> g_vT [bh][d][s], tf32-rounded
__global__ __launch_bounds__(256) void transpose_v_kernel()
{
    __shared__ float t[32][33];
    const int bh = blockIdx.z;
    const float* in = g_v + (size_t)bh * SS * DH;
    float* outp = g_vT + (size_t)bh * DH * SS;
    const int s0 = blockIdx.x * 32, d0 = blockIdx.y * 32;
    const int tx = threadIdx.x, ty = threadIdx.y;
#pragma unroll
    for (int i = 0; i < 32; i += 8)
        t[ty + i][tx] = in[(size_t)(s0 + ty + i) * DH + d0 + tx];
    __syncthreads();
#pragma unroll
    for (int i = 0; i < 32; i += 8)
        outp[(size_t)(d0 + ty + i) * SS + s0 + tx] = tf32r(t[tx][ty + i]);
}

// permute b1: out[2c]=b1[c], out[2c+1]=b1[2048+c]
__global__ __launch_bounds__(256) void permute_b1_kernel(const float* __restrict__ b1)
{
    const int c = blockIdx.x * 256 + threadIdx.x;   // 0..2047
    g_pb1[2 * c]     = b1[c];
    g_pb1[2 * c + 1] = b1[FF_HID + c];
}

__global__ __launch_bounds__(256) void round_copy_kernel(
    const float* __restrict__ in, float* __restrict__ out)
{
    const int i = blockIdx.x * 256 + threadIdx.x;
    float4 v = ((const float4*)in)[i];
    v.x = tf32r(v.x); v.y = tf32r(v.y); v.z = tf32r(v.z); v.w = tf32r(v.w);
    ((float4*)out)[i] = v;
}

// ---------------------------------------------------------------------------
// l2norm + scale + xpos-RoPE, scatter q/k/v to [B*H, S, 64]
// q,k written tf32-rounded; q pre-scaled by 0.125 (softmax scale)
// ---------------------------------------------------------------------------
__global__ __launch_bounds__(256) void normrope_kernel(
    const float* __restrict__ q_scale, const float* __restrict__ k_scale)
{
    const int w    = blockIdx.x * 8 + (threadIdx.x >> 5);
    const int lane = threadIdx.x & 31;

    const int h    = w & 15;
    const int spos = (w >> 4) & (SS - 1);
    const int b    = w >> 15;
    const int bs   = (b * SS + spos);

    const float* base = g_qkv + (size_t)bs * N_QKV + h * 192;

    float q0 = base[lane],       q1 = base[lane + 32];
    float k0 = base[64 + lane],  k1 = base[96 + lane];
    float v0 = base[128 + lane], v1 = base[160 + lane];

    float sq = q0 * q0 + q1 * q1;
    float sk = k0 * k0 + k1 * k1;
#pragma unroll
    for (int o = 16; o > 0; o >>= 1) {
        sq += __shfl_xor_sync(0xffffffffu, sq, o);
        sk += __shfl_xor_sync(0xffffffffu, sk, o);
    }
    const float invq = 1.0f / fmaxf(sqrtf(sq), 1e-12f);
    const float invk = 1.0f / fmaxf(sqrtf(sk), 1e-12f);

    q0 = q0 * invq * q_scale[lane];
    q1 = q1 * invq * q_scale[lane + 32];
    k0 = k0 * invk * k_scale[lane];
    k1 = k1 * invk * k_scale[lane + 32];

    const float inv_freq = expf(-((2.0f * lane) / 64.0f) * 9.210340371976184f);
    const float f = (float)spos * inv_freq;
    float sn, cs;
    sincosf(f, &sn, &cs);
    const float power = ((float)spos - 1024.0f) * (1.0f / 512.0f);
    const float bse   = (2.0f * lane + 25.6f) * (1.0f / 89.6f);
    const float sc    = powf(bse, power);
    const float sci   = 1.0f / sc;

    const float q0r = (q0 * cs - q1 * sn) * sc;
    const float q1r = (q1 * cs + q0 * sn) * sc;
    const float k0r = (k0 * cs - k1 * sn) * sci;
    const float k1r = (k1 * cs + k0 * sn) * sci;

    const int bh = b * HH + h;
    const size_t o = ((size_t)bh * SS + spos) * DH;
    g_q[o + lane]      = tf32r(q0r * 0.125f);
    g_q[o + lane + 32] = tf32r(q1r * 0.125f);
    g_k[o + lane]      = tf32r(k0r);
    g_k[o + lane + 32] = tf32r(k1r);
    g_v[o + lane] = v0;   g_v[o + lane + 32] = v1;
}

// ---------------------------------------------------------------------------
// Flash attention via mma.sync tf32.
// ---------------------------------------------------------------------------
#define ATT_PAD 68
#define ATT_QF   (128 * ATT_PAD)           // Q floats
#define ATT_STF  (2 * 64 * ATT_PAD)        // per-stage floats (K + V^T)

__global__ __launch_bounds__(128) void attn_mma_kernel()
{
    extern __shared__ float sm[];
    float* Qs = sm;
    float* Stg = sm + ATT_QF;

    const int bh = blockIdx.x;
    const int q0 = blockIdx.y * 128;
    const int tid = threadIdx.x, wid = tid >> 5, lane = tid & 31;
    const int g = lane >> 2, tg = lane & 3;
    const uint32_t smbase = smem_u32(sm);

    const float* Q  = g_q + ((size_t)bh * SS + q0) * DH;
    const float* K  = g_k + (size_t)bh * SS * DH;
    const float* Vt = g_vT + (size_t)bh * DH * SS;

    for (int i = tid; i < 128 * 16; i += 128) {
        const int r = i >> 4, c4 = (i & 15) * 4;
        *(float4*)(&Qs[r * ATT_PAD + c4]) = *(const float4*)(Q + r * DH + c4);
    }

    auto load_kv = [&](int t, int s) {
        const uint32_t kB = smbase + (ATT_QF + s * ATT_STF) * 4;
        const uint32_t vB = kB + 64 * ATT_PAD * 4;
        const float* Kg = K + (size_t)t * 64 * DH;
#pragma unroll
        for (int i = 0; i < 8; i++) {
            const int idx = tid + 128 * i;
            const int r = idx >> 4, c4 = (idx & 15) * 4;
            cpasync16(kB + (uint32_t)(r * ATT_PAD + c4) * 4, Kg + r * DH + c4);
            cpasync16(vB + (uint32_t)(r * ATT_PAD + c4) * 4, Vt + (size_t)r * SS + t * 64 + c4);
        }
        cp_commit();
    };

    load_kv(0, 0);

    float acc[2][8][4] = {};
    float mrow[4] = {-1e30f, -1e30f, -1e30f, -1e30f};
    float lrow[4] = {};

    const int NT = SS / 64;
    for (int t = 0; t < NT; t++) {
        const int s = t & 1;
        if (t + 1 < NT) load_kv(t + 1, s ^ 1);
        if (t + 1 < NT) cp_wait1(); else cp_wait0();
        __syncthreads();

        const uint32_t* Ks = (const uint32_t*)(Stg + s * ATT_STF);
        const uint32_t* Vs = Ks + 64 * ATT_PAD;

        float sc[2][8][4] = {};
#pragma unroll
        for (int kt = 0; kt < 8; kt++) {
            uint32_t aq[2][4], bk[8][2];
#pragma unroll
            for (int mi = 0; mi < 2; mi++) {
                const uint32_t* ap = (const uint32_t*)Qs + (wid * 32 + mi * 16 + g) * ATT_PAD + kt * 8 + tg;
                aq[mi][0] = ap[0];
                aq[mi][1] = ap[8 * ATT_PAD];
                aq[mi][2] = ap[4];
                aq[mi][3] = ap[8 * ATT_PAD + 4];
            }
#pragma unroll
            for (int ni = 0; ni < 8; ni++) {
                const uint32_t* bp = Ks + (ni * 8 + g) * ATT_PAD + kt * 8 + tg;
                bk[ni][0] = bp[0];
                bk[ni][1] = bp[4];
            }
#pragma unroll
            for (int mi = 0; mi < 2; mi++)
#pragma unroll
                for (int ni = 0; ni < 8; ni++)
                    mma_tf32(sc[mi][ni], aq[mi], bk[ni]);
        }

#pragma unroll
        for (int mi = 0; mi < 2; mi++) {
#pragma unroll
            for (int hf = 0; hf < 2; hf++) {
                const int r = mi * 2 + hf;
                float mx = -1e30f;
#pragma unroll
                for (int ni = 0; ni < 8; ni++)
                    mx = fmaxf(mx, fmaxf(sc[mi][ni][hf * 2], sc[mi][ni][hf * 2 + 1]));
                mx = fmaxf(mx, __shfl_xor_sync(0xffffffffu, mx, 1));
                mx = fmaxf(mx, __shfl_xor_sync(0xffffffffu, mx, 2));
                const float newm = fmaxf(mrow[r], mx);
                const float corr = __expf(mrow[r] - newm);
                mrow[r] = newm;
                float sum = 0.0f;
#pragma unroll
                for (int ni = 0; ni < 8; ni++) {
                    const float p0 = __expf(sc[mi][ni][hf * 2]     - newm);
                    const float p1 = __expf(sc[mi][ni][hf * 2 + 1] - newm);
                    sum += p0 + p1;
                    sc[mi][ni][hf * 2]     = p0;
                    sc[mi][ni][hf * 2 + 1] = p1;
                }
                sum += __shfl_xor_sync(0xffffffffu, sum, 1);
                sum += __shfl_xor_sync(0xffffffffu, sum, 2);
                lrow[r] = lrow[r] * corr + sum;
#pragma unroll
                for (int nd = 0; nd < 8; nd++) {
                    acc[mi][nd][hf * 2]     *= corr;
                    acc[mi][nd][hf * 2 + 1] *= corr;
                }
            }
        }

        const int src0 = g * 4 + (tg >> 1);
        const int src1 = src0 + 2;
        const bool odd = tg & 1;
#pragma unroll
        for (int kt = 0; kt < 8; kt++) {
            uint32_t ap[2][4];
#pragma unroll
            for (int mi = 0; mi < 2; mi++) {
                const float c0 = sc[mi][kt][0], c1 = sc[mi][kt][1];
                const float c2 = sc[mi][kt][2], c3 = sc[mi][kt][3];
                const float v00 = __shfl_sync(0xffffffffu, c0, src0);
                const float v01 = __shfl_sync(0xffffffffu, c1, src0);
                const float v10 = __shfl_sync(0xffffffffu, c0, src1);
                const float v11 = __shfl_sync(0xffffffffu, c1, src1);
                const float v20 = __shfl_sync(0xffffffffu, c2, src0);
                const float v21 = __shfl_sync(0xffffffffu, c3, src0);
                const float v30 = __shfl_sync(0xffffffffu, c2, src1);
                const float v31 = __shfl_sync(0xffffffffu, c3, src1);
                ap[mi][0] = __float_as_uint(tf32r(odd ? v01 : v00));
                ap[mi][1] = __float_as_uint(tf32r(odd ? v21 : v20));
                ap[mi][2] = __float_as_uint(tf32r(odd ? v11 : v10));
                ap[mi][3] = __float_as_uint(tf32r(odd ? v31 : v30));
            }
            uint32_t bv[8][2];
#pragma unroll
            for (int nd = 0; nd < 8; nd++) {
                const uint32_t* bp = Vs + (nd * 8 + g) * ATT_PAD + kt * 8 + tg;
                bv[nd][0] = bp[0];
                bv[nd][1] = bp[4];
            }
#pragma unroll
            for (int mi = 0; mi < 2; mi++)
#pragma unroll
                for (int nd = 0; nd < 8; nd++)
                    mma_tf32(acc[mi][nd], ap[mi], bv[nd]);
        }
        __syncthreads();
    }

    const int b = bh >> 4, h = bh & 15;
#pragma unroll
    for (int mi = 0; mi < 2; mi++) {
        const int row0 = q0 + wid * 32 + mi * 16 + g;
        const float inv0 = 1.0f / lrow[mi * 2 + 0];
        const float inv1 = 1.0f / lrow[mi * 2 + 1];
#pragma unroll
        for (int nd = 0; nd < 8; nd++) {
            const int col = h * 64 + nd * 8 + tg * 2;
            float2 o0, o1;
            o0.x = acc[mi][nd][0] * inv0; o0.y = acc[mi][nd][1] * inv0;
            o1.x = acc[mi][nd][2] * inv1; o1.y = acc[mi][nd][3] * inv1;
            *(float2*)(g_attn + ((size_t)(b * SS + row0)) * DD + col) = o0;
            *(float2*)(g_attn + ((size_t)(b * SS + row0 + 8)) * DD + col) = o1;
        }
    }
}

// ---------------------------------------------------------------------------
// LayerNorm; writes fp32 g_ln (residual) and tf32-rounded g_lnr (GEMM A)
// ---------------------------------------------------------------------------
__global__ __launch_bounds__(256) void ln_kernel(
    const float* __restrict__ gw, const float* __restrict__ bw)
{
    __shared__ float red[64];
    const int r = blockIdx.x;
    const int t = threadIdx.x;

    const float4 x = ((const float4*)(g_attn + (size_t)r * DD))[t];
    float s  = x.x + x.y + x.z + x.w;
    float ss = x.x*x.x + x.y*x.y + x.z*x.z + x.w*x.w;
#pragma unroll
    for (int o = 16; o > 0; o >>= 1) {
        s  += __shfl_xor_sync(0xffffffffu, s,  o);
        ss += __shfl_xor_sync(0xffffffffu, ss, o);
    }
    if ((t & 31) == 0) { red[t >> 5] = s; red[32 + (t >> 5)] = ss; }
    __syncthreads();
    if (t == 0) {
        float S = 0, SSum = 0;
#pragma unroll
        for (int i = 0; i < 8; i++) { S += red[i]; SSum += red[32 + i]; }
        red[0] = S; red[32] = SSum;
    }
    __syncthreads();
    const float mu  = red[0]  * (1.0f / DD);
    const float var = red[32] * (1.0f / DD) - mu * mu;
    const float inv = rsqrtf(var + 1e-5f);

    const int c = t * 4;
    float4 o;
    o.x = (x.x - mu) * inv * gw[c + 0] + bw[c + 0];
    o.y = (x.y - mu) * inv * gw[c + 1] + bw[c + 1];
    o.z = (x.z - mu) * inv * gw[c + 2] + bw[c + 2];
    o.w = (x.w - mu) * inv * gw[c + 3] + bw[c + 3];
    ((float4*)(g_ln + (size_t)r * DD))[t] = o;
    float4 orr;
    orr.x = tf32r(o.x); orr.y = tf32r(o.y); orr.z = tf32r(o.z); orr.w = tf32r(o.w);
    ((float4*)(g_lnr + (size_t)r * DD))[t] = orr;
}

// ---------------------------------------------------------------------------
extern "C" void kernel_launch(void* const* d_in, const int* in_sizes, int n_in,
                              void* d_out, int out_size)
{
    const float* q       = (const float*)d_in[0];
    const float* Wqkv    = (const float*)d_in[3];
    const float* bqkv    = (const float*)d_in[4];
    const float* q_scale = (const float*)d_in[5];
    const float* k_scale = (const float*)d_in[6];
    const float* ln_g    = (const float*)d_in[7];
    const float* ln_b    = (const float*)d_in[8];
    const float* W1      = (const float*)d_in[9];
    const float* b1      = (const float*)d_in[10];
    const float* W2      = (const float*)d_in[11];
    const float* b2      = (const float*)d_in[12];
    float* out = (float*)d_out;

    float *p_qkv, *p_aq, *p_ln, *p_lnr, *p_gate, *p_wqkvT, *p_w1T, *p_w2T, *p_pb1;
    cudaGetSymbolAddress((void**)&p_qkv,   g_qkv);
    cudaGetSymbolAddress((void**)&p_aq,    g_aq);
    cudaGetSymbolAddress((void**)&p_ln,    g_ln);
    cudaGetSymbolAddress((void**)&p_lnr,   g_lnr);
    cudaGetSymbolAddress((void**)&p_gate,  g_gate);
    cudaGetSymbolAddress((void**)&p_wqkvT, g_wqkvT);
    cudaGetSymbolAddress((void**)&p_w1T,   g_w1T);
    cudaGetSymbolAddress((void**)&p_w2T,   g_w2T);
    cudaGetSymbolAddress((void**)&p_pb1,   g_pb1);

    const int GSMEM = STAGE_F * 2 * 4;                    // 73728 bytes
    const int ASMEM = (ATT_QF + 2 * ATT_STF) * 4;         // 104448 bytes
    cudaFuncSetAttribute(gemm_mma_kernel<false>, cudaFuncAttributeMaxDynamicSharedMemorySize, GSMEM);
    cudaFuncSetAttribute(gemm_mma_kernel<true>,  cudaFuncAttributeMaxDynamicSharedMemorySize, GSMEM);
    cudaFuncSetAttribute(attn_mma_kernel, cudaFuncAttributeMaxDynamicSharedMemorySize, ASMEM);

    // launches 0-4 (so QKV GEMM is launch index 5 for the ncu -s 5 capture)
    transpose_round_kernel<0><<<dim3(N_QKV / 32, DD / 32), dim3(32, 8)>>>(Wqkv, p_wqkvT, DD, N_QKV);
    transpose_round_kernel<1><<<dim3(FF_IN / 32, DD / 32), dim3(32, 8)>>>(W1, p_w1T, DD, FF_IN);
    transpose_round_kernel<0><<<dim3(DD / 32, FF_HID / 32), dim3(32, 8)>>>(W2, p_w2T, FF_HID, DD);
    permute_b1_kernel<<<FF_HID / 256, 256>>>(b1);
    round_copy_kernel<<<ROWS * DD / 4 / 256, 256>>>(q, p_aq);

    // 5) QKV projection (profiled launch)
    gemm_mma_kernel<false><<<dim3(N_QKV / GBN, ROWS / GBM), 256, GSMEM>>>(
        p_aq, p_wqkvT, bqkv, nullptr, p_qkv, N_QKV, DD);

    // 6) l2norm + scale + RoPE
    normrope_kernel<<<(BB * SS * HH) / 8, 256>>>(q_scale, k_scale);

    // 7) V transpose per head
    transpose_v_kernel<<<dim3(SS / 32, DH / 32, BB * HH), dim3(32, 8)>>>();

    // 8) attention (tensor cores)
    attn_mma_kernel<<<dim3(BB * HH, SS / 128), 128, ASMEM>>>();

    // 9) LayerNorm
    ln_kernel<<<ROWS, 256>>>(ln_g, ln_b);

    // 10) FF1 + fused SwiGLU (x/gate interleaved weights), writes g_gate
    gemm_mma_kernel<true><<<dim3(FF_IN / GBN, ROWS / GBM), 256, GSMEM>>>(
        p_lnr, p_w1T, p_pb1, nullptr, p_gate, FF_IN, DD);

    // 11) FF2 + bias + residual(ln)
    gemm_mma_kernel<false><<<dim3(DD / GBN, ROWS / GBM), 256, GSMEM>>>(
        p_gate, p_w2T, b2, p_ln, out, DD, FF_HID);
}

// round 12
// speedup vs baseline: 1.5380x; 1.5380x over previous
#include <cuda_runtime.h>
#include <math.h>
#include <stdint.h>

// Problem constants
#define BB 4
#define SS 2048
#define HH 16
#define DH 64
#define DD 1024            // H*DH
#define ROWS (BB*SS)       // 8192
#define N_QKV (3*DD)       // 3072
#define FF_IN 4096
#define FF_HID 2048

// Scratch (device globals; no allocation)
__device__ float g_qkv [(size_t)ROWS * N_QKV];   // [B*S, 3072]
__device__ float g_aq  [(size_t)ROWS * DD];      // tf32-rounded q
__device__ float g_q   [(size_t)ROWS * DD];      // [B*H, S, 64] tf32, pre-scaled 0.125
__device__ float g_k   [(size_t)ROWS * DD];      // [B*H, S, 64] tf32
__device__ float g_v   [(size_t)ROWS * DD];      // [B*H, S, 64] raw
__device__ float g_vT  [(size_t)ROWS * DD];      // [B*H, 64, S] tf32
__device__ float g_attn[(size_t)ROWS * DD];      // [B*S, 1024]
__device__ float g_ln  [(size_t)ROWS * DD];      // LN out (fp32, residual)
__device__ float g_lnr [(size_t)ROWS * DD];      // LN out tf32-rounded (GEMM A)
__device__ float g_gate[(size_t)ROWS * FF_HID];  // [B*S, 2048] tf32-rounded
__device__ float g_wqkvT[(size_t)N_QKV * DD];    // [3072, 1024]
__device__ float g_w1T  [(size_t)FF_IN * DD];    // [4096, 1024] x/gate interleaved
__device__ float g_w2T  [(size_t)DD * FF_HID];   // [1024, 2048]
__device__ float g_pb1  [FF_IN];                 // permuted b1

// ---------------------------------------------------------------------------
// helpers
// ---------------------------------------------------------------------------
__device__ __forceinline__ float tf32r(float x) {
    float o; asm("cvt.rna.tf32.f32 %0, %1;" : "=f"(o) : "f"(x)); return o;
}
__device__ __forceinline__ uint32_t smem_u32(const void* p) {
    uint32_t a;
    asm("{ .reg .u64 t; cvta.to.shared.u64 t, %1; cvt.u32.u64 %0, t; }" : "=r"(a) : "l"(p));
    return a;
}
__device__ __forceinline__ void cpasync16(uint32_t dst, const void* src) {
    asm volatile("cp.async.cg.shared.global [%0], [%1], 16;" :: "r"(dst), "l"(src) : "memory");
}
__device__ __forceinline__ void cp_commit() {
    asm volatile("cp.async.commit_group;" ::: "memory");
}
__device__ __forceinline__ void cp_wait1() {
    asm volatile("cp.async.wait_group 1;" ::: "memory");
}
__device__ __forceinline__ void cp_wait0() {
    asm volatile("cp.async.wait_group 0;" ::: "memory");
}
__device__ __forceinline__ void mma_tf32(float* c, const uint32_t* a, const uint32_t* b) {
    asm volatile(
        "mma.sync.aligned.m16n8k8.row.col.f32.tf32.tf32.f32 "
        "{%0,%1,%2,%3}, {%4,%5,%6,%7}, {%8,%9}, {%0,%1,%2,%3};"
        : "+f"(c[0]), "+f"(c[1]), "+f"(c[2]), "+f"(c[3])
        : "r"(a[0]), "r"(a[1]), "r"(a[2]), "r"(a[3]), "r"(b[0]), "r"(b[1]));
}

// ---------------------------------------------------------------------------
// tf32 mma.sync GEMM: C[M,N] = A[M,K] @ Bt[N,K]^T + bias (+ res)
// SWIGLU=true: N cols are (x,gate) interleaved pairs; writes silu(g)*x to
// C[M, N/2] (tf32-rounded), res unused.
// ---------------------------------------------------------------------------
#define GBM 128
#define GBN 128
#define GBK 32
#define APAD 36
#define STAGE_F (2 * 128 * APAD)   // floats per stage (A+B)

template<bool SWIGLU>
__global__ __launch_bounds__(256) void gemm_mma_kernel(
    const float* __restrict__ A, const float* __restrict__ Bt,
    const float* __restrict__ bias, const float* __restrict__ res,
    float* __restrict__ C, int N, int K)
{
    extern __shared__ float sm[];
    const int tid = threadIdx.x;
    const int wid = tid >> 5, lane = tid & 31;
    const int g = lane >> 2, tg = lane & 3;
    const int warp_m = wid & 3, warp_n = wid >> 2;
    const int m0 = blockIdx.y * GBM, n0 = blockIdx.x * GBN;
    const uint32_t smbase = smem_u32(sm);

    float acc[2][8][4] = {};

    const int NIT = K >> 5;

    auto load_stage = [&](int it, int s) {
        const int k0 = it * GBK;
        const uint32_t aB = smbase + (uint32_t)s * STAGE_F * 4;
        const uint32_t bB = aB + 128 * APAD * 4;
#pragma unroll
        for (int i = 0; i < 4; i++) {
            const int idx = tid + 256 * i;
            const int row = idx >> 3, c4 = (idx & 7) * 4;
            cpasync16(aB + (uint32_t)(row * APAD + c4) * 4,
                      A  + (size_t)(m0 + row) * K + k0 + c4);
            cpasync16(bB + (uint32_t)(row * APAD + c4) * 4,
                      Bt + (size_t)(n0 + row) * K + k0 + c4);
        }
        cp_commit();
    };

    load_stage(0, 0);

    for (int it = 0; it < NIT; it++) {
        const int s = it & 1;
        if (it + 1 < NIT) load_stage(it + 1, s ^ 1);
        if (it + 1 < NIT) cp_wait1(); else cp_wait0();
        __syncthreads();

        const uint32_t* Asm = (const uint32_t*)(sm + s * STAGE_F);
        const uint32_t* Bsm = Asm + 128 * APAD;

#pragma unroll
        for (int kt = 0; kt < 4; kt++) {
            const int k = kt * 8;
            uint32_t a[2][4], b[8][2];
#pragma unroll
            for (int mi = 0; mi < 2; mi++) {
                const uint32_t* ap = Asm + (warp_m * 32 + mi * 16 + g) * APAD + k + tg;
                a[mi][0] = ap[0];
                a[mi][1] = ap[8 * APAD];
                a[mi][2] = ap[4];
                a[mi][3] = ap[8 * APAD + 4];
            }
#pragma unroll
            for (int ni = 0; ni < 8; ni++) {
                const uint32_t* bp = Bsm + (warp_n * 64 + ni * 8 + g) * APAD + k + tg;
                b[ni][0] = bp[0];
                b[ni][1] = bp[4];
            }
#pragma unroll
            for (int mi = 0; mi < 2; mi++)
#pragma unroll
                for (int ni = 0; ni < 8; ni++)
                    mma_tf32(acc[mi][ni], a[mi], b[ni]);
        }
        __syncthreads();
    }

    if (SWIGLU) {
        // cols (even, odd) = (x, gate); out[col/2] = silu(gate)*x, C is [M, N/2]
        const int NH = N >> 1;
#pragma unroll
        for (int mi = 0; mi < 2; mi++) {
            const int row0 = m0 + warp_m * 32 + mi * 16 + g;
#pragma unroll
            for (int ni = 0; ni < 8; ni++) {
                const int col = n0 + warp_n * 64 + ni * 8 + tg * 2;
                const float2 bv = *(const float2*)(bias + col);
                const float x0 = acc[mi][ni][0] + bv.x;
                const float g0 = acc[mi][ni][1] + bv.y;
                const float x1 = acc[mi][ni][2] + bv.x;
                const float g1 = acc[mi][ni][3] + bv.y;
                const float o0 = tf32r(x0 * g0 * __frcp_rn(1.0f + __expf(-g0)));
                const float o1 = tf32r(x1 * g1 * __frcp_rn(1.0f + __expf(-g1)));
                // pair adjacent output columns across tg neighbors -> float2
                const float p0 = __shfl_xor_sync(0xffffffffu, o0, 1);
                const float p1 = __shfl_xor_sync(0xffffffffu, o1, 1);
                const int cp = col >> 1;   // output col owned by this lane
                if ((tg & 1) == 0) {
                    *(float2*)(C + (size_t)row0 * NH + cp) = make_float2(o0, p0);
                } else {
                    *(float2*)(C + (size_t)(row0 + 8) * NH + cp - 1) = make_float2(p1, o1);
                }
            }
        }
    } else {
#pragma unroll
        for (int mi = 0; mi < 2; mi++) {
            const int row0 = m0 + warp_m * 32 + mi * 16 + g;
#pragma unroll
            for (int ni = 0; ni < 8; ni++) {
                const int col = n0 + warp_n * 64 + ni * 8 + tg * 2;
                const float2 bv = *(const float2*)(bias + col);
                float2 o0, o1;
                o0.x = acc[mi][ni][0] + bv.x;
                o0.y = acc[mi][ni][1] + bv.y;
                o1.x = acc[mi][ni][2] + bv.x;
                o1.y = acc[mi][ni][3] + bv.y;
                if (res) {
                    const float2 r0 = *(const float2*)(res + (size_t)row0 * N + col);
                    const float2 r1 = *(const float2*)(res + (size_t)(row0 + 8) * N + col);
                    o0.x += r0.x; o0.y += r0.y; o1.x += r1.x; o1.y += r1.y;
                }
                *(float2*)(C + (size_t)row0 * N + col) = o0;
                *(float2*)(C + (size_t)(row0 + 8) * N + col) = o1;
            }
        }
    }
}

// ---------------------------------------------------------------------------
// Transpose + tf32-round: out[c*R + r] = rnd(in[r*Cc + c])
// PERM=1: output row index remapped for x/gate interleave (Cc=4096 case)
// ---------------------------------------------------------------------------
template<int PERM>
__global__ __launch_bounds__(256) void transpose_round_kernel(
    const float* __restrict__ in, float* __restrict__ out, int R, int Cc)
{
    __shared__ float t[32][33];
    const int bx = blockIdx.x, by = blockIdx.y;
    const int tx = threadIdx.x, ty = threadIdx.y;
#pragma unroll
    for (int i = 0; i < 32; i += 8)
        t[ty + i][tx] = in[(size_t)(by * 32 + ty + i) * Cc + bx * 32 + tx];
    __syncthreads();
#pragma unroll
    for (int i = 0; i < 32; i += 8) {
        int r = bx * 32 + ty + i;
        if (PERM) r = (r < 2048) ? (2 * r) : (2 * (r - 2048) + 1);
        out[(size_t)r * R + by * 32 + tx] = tf32r(t[tx][ty + i]);
    }
}

// Batched V transpose per head: g_v [bh][s][d] -> g_vT [bh][d][s], tf32-rounded
__global__ __launch_bounds__(256) void transpose_v_kernel()
{
    __shared__ float t[32][33];
    const int bh = blockIdx.z;
    const float* in = g_v + (size_t)bh * SS * DH;
    float* outp = g_vT + (size_t)bh * DH * SS;
    const int s0 = blockIdx.x * 32, d0 = blockIdx.y * 32;
    const int tx = threadIdx.x, ty = threadIdx.y;
#pragma unroll
    for (int i = 0; i < 32; i += 8)
        t[ty + i][tx] = in[(size_t)(s0 + ty + i) * DH + d0 + tx];
    __syncthreads();
#pragma unroll
    for (int i = 0; i < 32; i += 8)
        outp[(size_t)(d0 + ty + i) * SS + s0 + tx] = tf32r(t[tx][ty + i]);
}

// permute b1: out[2c]=b1[c], out[2c+1]=b1[2048+c]
__global__ __launch_bounds__(256) void permute_b1_kernel(const float* __restrict__ b1)
{
    const int c = blockIdx.x * 256 + threadIdx.x;   // 0..2047
    g_pb1[2 * c]     = b1[c];
    g_pb1[2 * c + 1] = b1[FF_HID + c];
}

__global__ __launch_bounds__(256) void round_copy_kernel(
    const float* __restrict__ in, float* __restrict__ out)
{
    const int i = blockIdx.x * 256 + threadIdx.x;
    float4 v = ((const float4*)in)[i];
    v.x = tf32r(v.x); v.y = tf32r(v.y); v.z = tf32r(v.z); v.w = tf32r(v.w);
    ((float4*)out)[i] = v;
}

// ---------------------------------------------------------------------------
// l2norm + scale + xpos-RoPE, scatter q/k/v to [B*H, S, 64]
// ---------------------------------------------------------------------------
__global__ __launch_bounds__(256) void normrope_kernel(
    const float* __restrict__ q_scale, const float* __restrict__ k_scale)
{
    const int w    = blockIdx.x * 8 + (threadIdx.x >> 5);
    const int lane = threadIdx.x & 31;

    const int h    = w & 15;
    const int spos = (w >> 4) & (SS - 1);
    const int b    = w >> 15;
    const int bs   = (b * SS + spos);

    const float* base = g_qkv + (size_t)bs * N_QKV + h * 192;

    float q0 = base[lane],       q1 = base[lane + 32];
    float k0 = base[64 + lane],  k1 = base[96 + lane];
    float v0 = base[128 + lane], v1 = base[160 + lane];

    float sq = q0 * q0 + q1 * q1;
    float sk = k0 * k0 + k1 * k1;
#pragma unroll
    for (int o = 16; o > 0; o >>= 1) {
        sq += __shfl_xor_sync(0xffffffffu, sq, o);
        sk += __shfl_xor_sync(0xffffffffu, sk, o);
    }
    const float invq = 1.0f / fmaxf(sqrtf(sq), 1e-12f);
    const float invk = 1.0f / fmaxf(sqrtf(sk), 1e-12f);

    q0 = q0 * invq * q_scale[lane];
    q1 = q1 * invq * q_scale[lane + 32];
    k0 = k0 * invk * k_scale[lane];
    k1 = k1 * invk * k_scale[lane + 32];

    const float inv_freq = __expf(-((2.0f * lane) / 64.0f) * 9.210340371976184f);
    const float f = (float)spos * inv_freq;
    float sn, cs;
    __sincosf(f, &sn, &cs);
    const float power = ((float)spos - 1024.0f) * (1.0f / 512.0f);
    const float bse   = (2.0f * lane + 25.6f) * (1.0f / 89.6f);
    const float sc    = __powf(bse, power);
    const float sci   = 1.0f / sc;

    const float q0r = (q0 * cs - q1 * sn) * sc;
    const float q1r = (q1 * cs + q0 * sn) * sc;
    const float k0r = (k0 * cs - k1 * sn) * sci;
    const float k1r = (k1 * cs + k0 * sn) * sci;

    const int bh = b * HH + h;
    const size_t o = ((size_t)bh * SS + spos) * DH;
    g_q[o + lane]      = tf32r(q0r * 0.125f);
    g_q[o + lane + 32] = tf32r(q1r * 0.125f);
    g_k[o + lane]      = tf32r(k0r);
    g_k[o + lane + 32] = tf32r(k1r);
    g_v[o + lane] = v0;   g_v[o + lane + 32] = v1;
}

// ---------------------------------------------------------------------------
// Flash attention via mma.sync tf32.
// ---------------------------------------------------------------------------
#define ATT_PAD 68
#define ATT_QF   (128 * ATT_PAD)           // Q floats
#define ATT_STF  (2 * 64 * ATT_PAD)        // per-stage floats (K + V^T)

__global__ __launch_bounds__(128) void attn_mma_kernel()
{
    extern __shared__ float sm[];
    float* Qs = sm;
    float* Stg = sm + ATT_QF;

    const int bh = blockIdx.x;
    const int q0 = blockIdx.y * 128;
    const int tid = threadIdx.x, wid = tid >> 5, lane = tid & 31;
    const int g = lane >> 2, tg = lane & 3;
    const uint32_t smbase = smem_u32(sm);

    const float* Q  = g_q + ((size_t)bh * SS + q0) * DH;
    const float* K  = g_k + (size_t)bh * SS * DH;
    const float* Vt = g_vT + (size_t)bh * DH * SS;

    for (int i = tid; i < 128 * 16; i += 128) {
        const int r = i >> 4, c4 = (i & 15) * 4;
        *(float4*)(&Qs[r * ATT_PAD + c4]) = *(const float4*)(Q + r * DH + c4);
    }

    auto load_kv = [&](int t, int s) {
        const uint32_t kB = smbase + (ATT_QF + s * ATT_STF) * 4;
        const uint32_t vB = kB + 64 * ATT_PAD * 4;
        const float* Kg = K + (size_t)t * 64 * DH;
#pragma unroll
        for (int i = 0; i < 8; i++) {
            const int idx = tid + 128 * i;
            const int r = idx >> 4, c4 = (idx & 15) * 4;
            cpasync16(kB + (uint32_t)(r * ATT_PAD + c4) * 4, Kg + r * DH + c4);
            cpasync16(vB + (uint32_t)(r * ATT_PAD + c4) * 4, Vt + (size_t)r * SS + t * 64 + c4);
        }
        cp_commit();
    };

    load_kv(0, 0);

    float acc[2][8][4] = {};
    float mrow[4] = {-1e30f, -1e30f, -1e30f, -1e30f};
    float lrow[4] = {};

    const int NT = SS / 64;
    for (int t = 0; t < NT; t++) {
        const int s = t & 1;
        if (t + 1 < NT) load_kv(t + 1, s ^ 1);
        if (t + 1 < NT) cp_wait1(); else cp_wait0();
        __syncthreads();

        const uint32_t* Ks = (const uint32_t*)(Stg + s * ATT_STF);
        const uint32_t* Vs = Ks + 64 * ATT_PAD;

        float sc[2][8][4] = {};
#pragma unroll
        for (int kt = 0; kt < 8; kt++) {
            uint32_t aq[2][4], bk[8][2];
#pragma unroll
            for (int mi = 0; mi < 2; mi++) {
                const uint32_t* ap = (const uint32_t*)Qs + (wid * 32 + mi * 16 + g) * ATT_PAD + kt * 8 + tg;
                aq[mi][0] = ap[0];
                aq[mi][1] = ap[8 * ATT_PAD];
                aq[mi][2] = ap[4];
                aq[mi][3] = ap[8 * ATT_PAD + 4];
            }
#pragma unroll
            for (int ni = 0; ni < 8; ni++) {
                const uint32_t* bp = Ks + (ni * 8 + g) * ATT_PAD + kt * 8 + tg;
                bk[ni][0] = bp[0];
                bk[ni][1] = bp[4];
            }
#pragma unroll
            for (int mi = 0; mi < 2; mi++)
#pragma unroll
                for (int ni = 0; ni < 8; ni++)
                    mma_tf32(sc[mi][ni], aq[mi], bk[ni]);
        }

#pragma unroll
        for (int mi = 0; mi < 2; mi++) {
#pragma unroll
            for (int hf = 0; hf < 2; hf++) {
                const int r = mi * 2 + hf;
                float mx = -1e30f;
#pragma unroll
                for (int ni = 0; ni < 8; ni++)
                    mx = fmaxf(mx, fmaxf(sc[mi][ni][hf * 2], sc[mi][ni][hf * 2 + 1]));
                mx = fmaxf(mx, __shfl_xor_sync(0xffffffffu, mx, 1));
                mx = fmaxf(mx, __shfl_xor_sync(0xffffffffu, mx, 2));
                const float newm = fmaxf(mrow[r], mx);
                const float corr = __expf(mrow[r] - newm);
                mrow[r] = newm;
                float sum = 0.0f;
#pragma unroll
                for (int ni = 0; ni < 8; ni++) {
                    const float p0 = __expf(sc[mi][ni][hf * 2]     - newm);
                    const float p1 = __expf(sc[mi][ni][hf * 2 + 1] - newm);
                    sum += p0 + p1;
                    sc[mi][ni][hf * 2]     = p0;
                    sc[mi][ni][hf * 2 + 1] = p1;
                }
                sum += __shfl_xor_sync(0xffffffffu, sum, 1);
                sum += __shfl_xor_sync(0xffffffffu, sum, 2);
                lrow[r] = lrow[r] * corr + sum;
#pragma unroll
                for (int nd = 0; nd < 8; nd++) {
                    acc[mi][nd][hf * 2]     *= corr;
                    acc[mi][nd][hf * 2 + 1] *= corr;
                }
            }
        }

        const int src0 = g * 4 + (tg >> 1);
        const int src1 = src0 + 2;
        const bool odd = tg & 1;
#pragma unroll
        for (int kt = 0; kt < 8; kt++) {
            uint32_t ap[2][4];
#pragma unroll
            for (int mi = 0; mi < 2; mi++) {
                const float c0 = sc[mi][kt][0], c1 = sc[mi][kt][1];
                const float c2 = sc[mi][kt][2], c3 = sc[mi][kt][3];
                const float v00 = __shfl_sync(0xffffffffu, c0, src0);
                const float v01 = __shfl_sync(0xffffffffu, c1, src0);
                const float v10 = __shfl_sync(0xffffffffu, c0, src1);
                const float v11 = __shfl_sync(0xffffffffu, c1, src1);
                const float v20 = __shfl_sync(0xffffffffu, c2, src0);
                const float v21 = __shfl_sync(0xffffffffu, c3, src0);
                const float v30 = __shfl_sync(0xffffffffu, c2, src1);
                const float v31 = __shfl_sync(0xffffffffu, c3, src1);
                ap[mi][0] = __float_as_uint(tf32r(odd ? v01 : v00));
                ap[mi][1] = __float_as_uint(tf32r(odd ? v21 : v20));
                ap[mi][2] = __float_as_uint(tf32r(odd ? v11 : v10));
                ap[mi][3] = __float_as_uint(tf32r(odd ? v31 : v30));
            }
            uint32_t bv[8][2];
#pragma unroll
            for (int nd = 0; nd < 8; nd++) {
                const uint32_t* bp = Vs + (nd * 8 + g) * ATT_PAD + kt * 8 + tg;
                bv[nd][0] = bp[0];
                bv[nd][1] = bp[4];
            }
#pragma unroll
            for (int mi = 0; mi < 2; mi++)
#pragma unroll
                for (int nd = 0; nd < 8; nd++)
                    mma_tf32(acc[mi][nd], ap[mi], bv[nd]);
        }
        __syncthreads();
    }

    const int b = bh >> 4, h = bh & 15;
#pragma unroll
    for (int mi = 0; mi < 2; mi++) {
        const int row0 = q0 + wid * 32 + mi * 16 + g;
        const float inv0 = 1.0f / lrow[mi * 2 + 0];
        const float inv1 = 1.0f / lrow[mi * 2 + 1];
#pragma unroll
        for (int nd = 0; nd < 8; nd++) {
            const int col = h * 64 + nd * 8 + tg * 2;
            float2 o0, o1;
            o0.x = acc[mi][nd][0] * inv0; o0.y = acc[mi][nd][1] * inv0;
            o1.x = acc[mi][nd][2] * inv1; o1.y = acc[mi][nd][3] * inv1;
            *(float2*)(g_attn + ((size_t)(b * SS + row0)) * DD + col) = o0;
            *(float2*)(g_attn + ((size_t)(b * SS + row0 + 8)) * DD + col) = o1;
        }
    }
}

// ---------------------------------------------------------------------------
// LayerNorm; writes fp32 g_ln (residual) and tf32-rounded g_lnr (GEMM A)
// ---------------------------------------------------------------------------
__global__ __launch_bounds__(256) void ln_kernel(
    const float* __restrict__ gw, const float* __restrict__ bw)
{
    __shared__ float red[64];
    const int r = blockIdx.x;
    const int t = threadIdx.x;

    const float4 x = ((const float4*)(g_attn + (size_t)r * DD))[t];
    float s  = x.x + x.y + x.z + x.w;
    float ss = x.x*x.x + x.y*x.y + x.z*x.z + x.w*x.w;
#pragma unroll
    for (int o = 16; o > 0; o >>= 1) {
        s  += __shfl_xor_sync(0xffffffffu, s,  o);
        ss += __shfl_xor_sync(0xffffffffu, ss, o);
    }
    if ((t & 31) == 0) { red[t >> 5] = s; red[32 + (t >> 5)] = ss; }
    __syncthreads();
    if (t == 0) {
        float S = 0, SSum = 0;
#pragma unroll
        for (int i = 0; i < 8; i++) { S += red[i]; SSum += red[32 + i]; }
        red[0] = S; red[32] = SSum;
    }
    __syncthreads();
    const float mu  = red[0]  * (1.0f / DD);
    const float var = red[32] * (1.0f / DD) - mu * mu;
    const float inv = rsqrtf(var + 1e-5f);

    const int c = t * 4;
    float4 o;
    o.x = (x.x - mu) * inv * gw[c + 0] + bw[c + 0];
    o.y = (x.y - mu) * inv * gw[c + 1] + bw[c + 1];
    o.z = (x.z - mu) * inv * gw[c + 2] + bw[c + 2];
    o.w = (x.w - mu) * inv * gw[c + 3] + bw[c + 3];
    ((float4*)(g_ln + (size_t)r * DD))[t] = o;
    float4 orr;
    orr.x = tf32r(o.x); orr.y = tf32r(o.y); orr.z = tf32r(o.z); orr.w = tf32r(o.w);
    ((float4*)(g_lnr + (size_t)r * DD))[t] = orr;
}

// ---------------------------------------------------------------------------
extern "C" void kernel_launch(void* const* d_in, const int* in_sizes, int n_in,
                              void* d_out, int out_size)
{
    const float* q       = (const float*)d_in[0];
    const float* Wqkv    = (const float*)d_in[3];
    const float* bqkv    = (const float*)d_in[4];
    const float* q_scale = (const float*)d_in[5];
    const float* k_scale = (const float*)d_in[6];
    const float* ln_g    = (const float*)d_in[7];
    const float* ln_b    = (const float*)d_in[8];
    const float* W1      = (const float*)d_in[9];
    const float* b1      = (const float*)d_in[10];
    const float* W2      = (const float*)d_in[11];
    const float* b2      = (const float*)d_in[12];
    float* out = (float*)d_out;

    float *p_qkv, *p_aq, *p_ln, *p_lnr, *p_gate, *p_wqkvT, *p_w1T, *p_w2T, *p_pb1;
    cudaGetSymbolAddress((void**)&p_qkv,   g_qkv);
    cudaGetSymbolAddress((void**)&p_aq,    g_aq);
    cudaGetSymbolAddress((void**)&p_ln,    g_ln);
    cudaGetSymbolAddress((void**)&p_lnr,   g_lnr);
    cudaGetSymbolAddress((void**)&p_gate,  g_gate);
    cudaGetSymbolAddress((void**)&p_wqkvT, g_wqkvT);
    cudaGetSymbolAddress((void**)&p_w1T,   g_w1T);
    cudaGetSymbolAddress((void**)&p_w2T,   g_w2T);
    cudaGetSymbolAddress((void**)&p_pb1,   g_pb1);

    const int GSMEM = STAGE_F * 2 * 4;                    // 73728 bytes
    const int ASMEM = (ATT_QF + 2 * ATT_STF) * 4;         // 104448 bytes
    cudaFuncSetAttribute(gemm_mma_kernel<false>, cudaFuncAttributeMaxDynamicSharedMemorySize, GSMEM);
    cudaFuncSetAttribute(gemm_mma_kernel<true>,  cudaFuncAttributeMaxDynamicSharedMemorySize, GSMEM);
    cudaFuncSetAttribute(attn_mma_kernel, cudaFuncAttributeMaxDynamicSharedMemorySize, ASMEM);

    transpose_round_kernel<0><<<dim3(N_QKV / 32, DD / 32), dim3(32, 8)>>>(Wqkv, p_wqkvT, DD, N_QKV);
    transpose_round_kernel<1><<<dim3(FF_IN / 32, DD / 32), dim3(32, 8)>>>(W1, p_w1T, DD, FF_IN);
    transpose_round_kernel<0><<<dim3(DD / 32, FF_HID / 32), dim3(32, 8)>>>(W2, p_w2T, FF_HID, DD);
    permute_b1_kernel<<<FF_HID / 256, 256>>>(b1);
    round_copy_kernel<<<ROWS * DD / 4 / 256, 256>>>(q, p_aq);

    // QKV projection
    gemm_mma_kernel<false><<<dim3(N_QKV / GBN, ROWS / GBM), 256, GSMEM>>>(
        p_aq, p_wqkvT, bqkv, nullptr, p_qkv, N_QKV, DD);

    // l2norm + scale + RoPE
    normrope_kernel<<<(BB * SS * HH) / 8, 256>>>(q_scale, k_scale);

    // V transpose per head
    transpose_v_kernel<<<dim3(SS / 32, DH / 32, BB * HH), dim3(32, 8)>>>();

    // attention (tensor cores)
    attn_mma_kernel<<<dim3(BB * HH, SS / 128), 128, ASMEM>>>();

    // LayerNorm
    ln_kernel<<<ROWS, 256>>>(ln_g, ln_b);

    // FF1 + fused SwiGLU (x/gate interleaved weights), writes g_gate
    gemm_mma_kernel<true><<<dim3(FF_IN / GBN, ROWS / GBM), 256, GSMEM>>>(
        p_lnr, p_w1T, p_pb1, nullptr, p_gate, FF_IN, DD);

    // FF2 + bias + residual(ln)
    gemm_mma_kernel<false><<<dim3(DD / GBN, ROWS / GBM), 256, GSMEM>>>(
        p_gate, p_w2T, b2, p_ln, out, DD, FF_HID);
}

// round 15
// speedup vs baseline: 1.5724x; 1.0224x over previous
#include <cuda_runtime.h>
#include <math.h>
#include <stdint.h>

// Problem constants
#define BB 4
#define SS 2048
#define HH 16
#define DH 64
#define DD 1024            // H*DH
#define ROWS (BB*SS)       // 8192
#define N_QKV (3*DD)       // 3072
#define FF_IN 4096
#define FF_HID 2048

// Scratch (device globals; no allocation)
__device__ float g_aq  [(size_t)ROWS * DD];      // tf32-rounded q input
__device__ float g_q   [(size_t)ROWS * DD];      // [B*H, S, 64] tf32, pre-scaled 0.125
__device__ float g_k   [(size_t)ROWS * DD];      // [B*H, S, 64] tf32
__device__ float g_vT  [(size_t)ROWS * DD];      // [B*H, 64, S] tf32
__device__ float g_attn[(size_t)ROWS * DD];      // [B*S, 1024]
__device__ float g_ln  [(size_t)ROWS * DD];      // LN out (fp32, residual)
__device__ float g_lnr [(size_t)ROWS * DD];      // LN out tf32-rounded (GEMM A)
__device__ float g_gate[(size_t)ROWS * FF_HID];  // [B*S, 2048] tf32-rounded
__device__ float g_wqkvT[(size_t)N_QKV * DD];    // [3072, 1024]
__device__ float g_w1T  [(size_t)FF_IN * DD];    // [4096, 1024] x/gate interleaved
__device__ float g_w2T  [(size_t)DD * FF_HID];   // [1024, 2048]
__device__ float g_pb1  [FF_IN];                 // permuted b1

// ---------------------------------------------------------------------------
// helpers
// ---------------------------------------------------------------------------
__device__ __forceinline__ float tf32r(float x) {
    float o; asm("cvt.rna.tf32.f32 %0, %1;" : "=f"(o) : "f"(x)); return o;
}
__device__ __forceinline__ uint32_t smem_u32(const void* p) {
    uint32_t a;
    asm("{ .reg .u64 t; cvta.to.shared.u64 t, %1; cvt.u32.u64 %0, t; }" : "=r"(a) : "l"(p));
    return a;
}
__device__ __forceinline__ void cpasync16(uint32_t dst, const void* src) {
    asm volatile("cp.async.cg.shared.global [%0], [%1], 16;" :: "r"(dst), "l"(src) : "memory");
}
__device__ __forceinline__ void cp_commit() {
    asm volatile("cp.async.commit_group;" ::: "memory");
}
__device__ __forceinline__ void cp_wait1() {
    asm volatile("cp.async.wait_group 1;" ::: "memory");
}
__device__ __forceinline__ void cp_wait0() {
    asm volatile("cp.async.wait_group 0;" ::: "memory");
}
__device__ __forceinline__ void mma_tf32(float* c, const uint32_t* a, const uint32_t* b) {
    asm volatile(
        "mma.sync.aligned.m16n8k8.row.col.f32.tf32.tf32.f32 "
        "{%0,%1,%2,%3}, {%4,%5,%6,%7}, {%8,%9}, {%0,%1,%2,%3};"
        : "+f"(c[0]), "+f"(c[1]), "+f"(c[2]), "+f"(c[3])
        : "r"(a[0]), "r"(a[1]), "r"(a[2]), "r"(a[3]), "r"(b[0]), "r"(b[1]));
}

// ---------------------------------------------------------------------------
// tf32 mma.sync GEMM: C[M,N] = A[M,K] @ Bt[N,K]^T + bias (+ res)
// MODE 0: plain (+res).   MODE 1: fused SwiGLU (interleaved x/gate cols).
// MODE 2: fused QKV epilogue: l2norm+scale+xpos-RoPE for q/k segments,
//         transposed store for v. Writes g_q / g_k / g_vT directly.
// ---------------------------------------------------------------------------
#define GBM 128
#define GBN 128
#define GBK 32
#define APAD 36
#define STAGE_F (2 * 128 * APAD)   // floats per stage (A+B)

template<int MODE>
__global__ __launch_bounds__(256) void gemm_mma_kernel(
    const float* __restrict__ A, const float* __restrict__ Bt,
    const float* __restrict__ bias, const float* __restrict__ res,
    const float* __restrict__ qsc, const float* __restrict__ ksc,
    float* __restrict__ C, int N, int K)
{
    extern __shared__ float sm[];
    const int tid = threadIdx.x;
    const int wid = tid >> 5, lane = tid & 31;
    const int g = lane >> 2, tg = lane & 3;
    const int warp_m = wid & 3, warp_n = wid >> 2;
    const int m0 = blockIdx.y * GBM, n0 = blockIdx.x * GBN;
    const uint32_t smbase = smem_u32(sm);

    float acc[2][8][4] = {};

    const int NIT = K >> 5;

    auto load_stage = [&](int it, int s) {
        const int k0 = it * GBK;
        const uint32_t aB = smbase + (uint32_t)s * STAGE_F * 4;
        const uint32_t bB = aB + 128 * APAD * 4;
#pragma unroll
        for (int i = 0; i < 4; i++) {
            const int idx = tid + 256 * i;
            const int row = idx >> 3, c4 = (idx & 7) * 4;
            cpasync16(aB + (uint32_t)(row * APAD + c4) * 4,
                      A  + (size_t)(m0 + row) * K + k0 + c4);
            cpasync16(bB + (uint32_t)(row * APAD + c4) * 4,
                      Bt + (size_t)(n0 + row) * K + k0 + c4);
        }
        cp_commit();
    };

    load_stage(0, 0);

    for (int it = 0; it < NIT; it++) {
        const int s = it & 1;
        if (it + 1 < NIT) load_stage(it + 1, s ^ 1);
        if (it + 1 < NIT) cp_wait1(); else cp_wait0();
        __syncthreads();

        const uint32_t* Asm = (const uint32_t*)(sm + s * STAGE_F);
        const uint32_t* Bsm = Asm + 128 * APAD;

#pragma unroll
        for (int kt = 0; kt < 4; kt++) {
            const int k = kt * 8;
            uint32_t a[2][4], b[8][2];
#pragma unroll
            for (int mi = 0; mi < 2; mi++) {
                const uint32_t* ap = Asm + (warp_m * 32 + mi * 16 + g) * APAD + k + tg;
                a[mi][0] = ap[0];
                a[mi][1] = ap[8 * APAD];
                a[mi][2] = ap[4];
                a[mi][3] = ap[8 * APAD + 4];
            }
#pragma unroll
            for (int ni = 0; ni < 8; ni++) {
                const uint32_t* bp = Bsm + (warp_n * 64 + ni * 8 + g) * APAD + k + tg;
                b[ni][0] = bp[0];
                b[ni][1] = bp[4];
            }
#pragma unroll
            for (int mi = 0; mi < 2; mi++)
#pragma unroll
                for (int ni = 0; ni < 8; ni++)
                    mma_tf32(acc[mi][ni], a[mi], b[ni]);
        }
        __syncthreads();
    }

    if (MODE == 2) {
        // --- fused QKV epilogue ---
        const int segcol = n0 + warp_n * 64;          // multiple of 64
        const int h   = segcol / 192;                 // head
        const int seg = (segcol >> 6) % 3;            // 0=q, 1=k, 2=v
#pragma unroll
        for (int mi = 0; mi < 2; mi++) {
#pragma unroll
            for (int hf = 0; hf < 2; hf++) {
                const int row  = m0 + warp_m * 32 + mi * 16 + g + hf * 8;  // b*S+s
                const int b    = row >> 11;
                const int spos = row & (SS - 1);
                float v[8][2];
#pragma unroll
                for (int ni = 0; ni < 8; ni++) {
#pragma unroll
                    for (int c = 0; c < 2; c++)
                        v[ni][c] = acc[mi][ni][hf * 2 + c] + bias[segcol + ni * 8 + tg * 2 + c];
                }
                if (seg == 2) {
                    // V: transposed store to g_vT[bh][d][s]
                    float* dst = g_vT + ((size_t)(b * HH + h) * DH) * SS + spos;
#pragma unroll
                    for (int ni = 0; ni < 8; ni++) {
#pragma unroll
                        for (int c = 0; c < 2; c++)
                            dst[(size_t)(ni * 8 + tg * 2 + c) * SS] = tf32r(v[ni][c]);
                    }
                } else {
                    // l2norm over the 64 dims (quad reduction)
                    float ssum = 0.0f;
#pragma unroll
                    for (int ni = 0; ni < 8; ni++)
                        ssum += v[ni][0] * v[ni][0] + v[ni][1] * v[ni][1];
                    ssum += __shfl_xor_sync(0xffffffffu, ssum, 1);
                    ssum += __shfl_xor_sync(0xffffffffu, ssum, 2);
                    const float inv = 1.0f / fmaxf(sqrtf(ssum), 1e-12f);
                    const float* sv = seg ? ksc : qsc;
#pragma unroll
                    for (int ni = 0; ni < 8; ni++) {
#pragma unroll
                        for (int c = 0; c < 2; c++)
                            v[ni][c] *= inv * sv[ni * 8 + tg * 2 + c];
                    }
                    // xpos-RoPE: pairs (d, d+32) = (ni, ni+4) same lane
                    const float power = ((float)spos - 1024.0f) * (1.0f / 512.0f);
                    float outv[8][2];
#pragma unroll
                    for (int ni = 0; ni < 4; ni++) {
#pragma unroll
                        for (int c = 0; c < 2; c++) {
                            const int j = ni * 8 + tg * 2 + c;
                            const float invf = __expf(-(float)j * 0.28782313662425574f);
                            float sn, cs;
                            __sincosf((float)spos * invf, &sn, &cs);
                            float sc = __powf((2.0f * j + 25.6f) * (1.0f / 89.6f), power);
                            if (seg == 1) sc = 1.0f / sc;
                            outv[ni][c]     = (v[ni][c] * cs - v[ni + 4][c] * sn) * sc;
                            outv[ni + 4][c] = (v[ni + 4][c] * cs + v[ni][c] * sn) * sc;
                        }
                    }
                    const float mul = seg ? 1.0f : 0.125f;   // fold softmax scale into q
                    float* dst = (seg ? g_k : g_q) + ((size_t)((b * HH + h) * SS + spos)) * DH;
#pragma unroll
                    for (int ni = 0; ni < 8; ni++) {
                        float2 w;
                        w.x = tf32r(outv[ni][0] * mul);
                        w.y = tf32r(outv[ni][1] * mul);
                        *(float2*)(dst + ni * 8 + tg * 2) = w;
                    }
                }
            }
        }
    } else if (MODE == 1) {
        // cols (even, odd) = (x, gate); out[col/2] = silu(gate)*x, C is [M, N/2]
        const int NH = N >> 1;
#pragma unroll
        for (int mi = 0; mi < 2; mi++) {
            const int row0 = m0 + warp_m * 32 + mi * 16 + g;
#pragma unroll
            for (int ni = 0; ni < 8; ni++) {
                const int col = n0 + warp_n * 64 + ni * 8 + tg * 2;
                const float2 bv = *(const float2*)(bias + col);
                const float x0 = acc[mi][ni][0] + bv.x;
                const float g0 = acc[mi][ni][1] + bv.y;
                const float x1 = acc[mi][ni][2] + bv.x;
                const float g1 = acc[mi][ni][3] + bv.y;
                const float o0 = tf32r(x0 * g0 * __frcp_rn(1.0f + __expf(-g0)));
                const float o1 = tf32r(x1 * g1 * __frcp_rn(1.0f + __expf(-g1)));
                const float p0 = __shfl_xor_sync(0xffffffffu, o0, 1);
                const float p1 = __shfl_xor_sync(0xffffffffu, o1, 1);
                const int cp = col >> 1;
                if ((tg & 1) == 0) {
                    *(float2*)(C + (size_t)row0 * NH + cp) = make_float2(o0, p0);
                } else {
                    *(float2*)(C + (size_t)(row0 + 8) * NH + cp - 1) = make_float2(p1, o1);
                }
            }
        }
    } else {
#pragma unroll
        for (int mi = 0; mi < 2; mi++) {
            const int row0 = m0 + warp_m * 32 + mi * 16 + g;
#pragma unroll
            for (int ni = 0; ni < 8; ni++) {
                const int col = n0 + warp_n * 64 + ni * 8 + tg * 2;
                const float2 bv = *(const float2*)(bias + col);
                float2 o0, o1;
                o0.x = acc[mi][ni][0] + bv.x;
                o0.y = acc[mi][ni][1] + bv.y;
                o1.x = acc[mi][ni][2] + bv.x;
                o1.y = acc[mi][ni][3] + bv.y;
                if (res) {
                    const float2 r0 = *(const float2*)(res + (size_t)row0 * N + col);
                    const float2 r1 = *(const float2*)(res + (size_t)(row0 + 8) * N + col);
                    o0.x += r0.x; o0.y += r0.y; o1.x += r1.x; o1.y += r1.y;
                }
                *(float2*)(C + (size_t)row0 * N + col) = o0;
                *(float2*)(C + (size_t)(row0 + 8) * N + col) = o1;
            }
        }
    }
}

// ---------------------------------------------------------------------------
// Transpose + tf32-round: out[c*R + r] = rnd(in[r*Cc + c])
// PERM=1: output row index remapped for x/gate interleave (Cc=4096 case)
// ---------------------------------------------------------------------------
template<int PERM>
__global__ __launch_bounds__(256) void transpose_round_kernel(
    const float* __restrict__ in, float* __restrict__ out, int R, int Cc)
{
    __shared__ float t[32][33];
    const int bx = blockIdx.x, by = blockIdx.y;
    const int tx = threadIdx.x, ty = threadIdx.y;
#pragma unroll
    for (int i = 0; i < 32; i += 8)
        t[ty + i][tx] = in[(size_t)(by * 32 + ty + i) * Cc + bx * 32 + tx];
    __syncthreads();
#pragma unroll
    for (int i = 0; i < 32; i += 8) {
        int r = bx * 32 + ty + i;
        if (PERM) r = (r < 2048) ? (2 * r) : (2 * (r - 2048) + 1);
        out[(size_t)r * R + by * 32 + tx] = tf32r(t[tx][ty + i]);
    }
}

// permute b1: out[2c]=b1[c], out[2c+1]=b1[2048+c]
__global__ __launch_bounds__(256) void permute_b1_kernel(const float* __restrict__ b1)
{
    const int c = blockIdx.x * 256 + threadIdx.x;   // 0..2047
    g_pb1[2 * c]     = b1[c];
    g_pb1[2 * c + 1] = b1[FF_HID + c];
}

__global__ __launch_bounds__(256) void round_copy_kernel(
    const float* __restrict__ in, float* __restrict__ out)
{
    const int i = blockIdx.x * 256 + threadIdx.x;
    float4 v = ((const float4*)in)[i];
    v.x = tf32r(v.x); v.y = tf32r(v.y); v.z = tf32r(v.z); v.w = tf32r(v.w);
    ((float4*)out)[i] = v;
}

// ---------------------------------------------------------------------------
// Flash attention via mma.sync tf32.
// ---------------------------------------------------------------------------
#define ATT_PAD 68
#define ATT_QF   (128 * ATT_PAD)           // Q floats
#define ATT_STF  (2 * 64 * ATT_PAD)        // per-stage floats (K + V^T)

__global__ __launch_bounds__(128) void attn_mma_kernel()
{
    extern __shared__ float sm[];
    float* Qs = sm;
    float* Stg = sm + ATT_QF;

    const int bh = blockIdx.x;
    const int q0 = blockIdx.y * 128;
    const int tid = threadIdx.x, wid = tid >> 5, lane = tid & 31;
    const int g = lane >> 2, tg = lane & 3;
    const uint32_t smbase = smem_u32(sm);

    const float* Q  = g_q + ((size_t)bh * SS + q0) * DH;
    const float* K  = g_k + (size_t)bh * SS * DH;
    const float* Vt = g_vT + (size_t)bh * DH * SS;

    for (int i = tid; i < 128 * 16; i += 128) {
        const int r = i >> 4, c4 = (i & 15) * 4;
        *(float4*)(&Qs[r * ATT_PAD + c4]) = *(const float4*)(Q + r * DH + c4);
    }

    auto load_kv = [&](int t, int s) {
        const uint32_t kB = smbase + (ATT_QF + s * ATT_STF) * 4;
        const uint32_t vB = kB + 64 * ATT_PAD * 4;
        const float* Kg = K + (size_t)t * 64 * DH;
#pragma unroll
        for (int i = 0; i < 8; i++) {
            const int idx = tid + 128 * i;
            const int r = idx >> 4, c4 = (idx & 15) * 4;
            cpasync16(kB + (uint32_t)(r * ATT_PAD + c4) * 4, Kg + r * DH + c4);
            cpasync16(vB + (uint32_t)(r * ATT_PAD + c4) * 4, Vt + (size_t)r * SS + t * 64 + c4);
        }
        cp_commit();
    };

    load_kv(0, 0);

    float acc[2][8][4] = {};
    float mrow[4] = {-1e30f, -1e30f, -1e30f, -1e30f};
    float lrow[4] = {};

    const int NT = SS / 64;
    for (int t = 0; t < NT; t++) {
        const int s = t & 1;
        if (t + 1 < NT) load_kv(t + 1, s ^ 1);
        if (t + 1 < NT) cp_wait1(); else cp_wait0();
        __syncthreads();

        const uint32_t* Ks = (const uint32_t*)(Stg + s * ATT_STF);
        const uint32_t* Vs = Ks + 64 * ATT_PAD;

        float sc[2][8][4] = {};
#pragma unroll
        for (int kt = 0; kt < 8; kt++) {
            uint32_t aq[2][4], bk[8][2];
#pragma unroll
            for (int mi = 0; mi < 2; mi++) {
                const uint32_t* ap = (const uint32_t*)Qs + (wid * 32 + mi * 16 + g) * ATT_PAD + kt * 8 + tg;
                aq[mi][0] = ap[0];
                aq[mi][1] = ap[8 * ATT_PAD];
                aq[mi][2] = ap[4];
                aq[mi][3] = ap[8 * ATT_PAD + 4];
            }
#pragma unroll
            for (int ni = 0; ni < 8; ni++) {
                const uint32_t* bp = Ks + (ni * 8 + g) * ATT_PAD + kt * 8 + tg;
                bk[ni][0] = bp[0];
                bk[ni][1] = bp[4];
            }
#pragma unroll
            for (int mi = 0; mi < 2; mi++)
#pragma unroll
                for (int ni = 0; ni < 8; ni++)
                    mma_tf32(sc[mi][ni], aq[mi], bk[ni]);
        }

#pragma unroll
        for (int mi = 0; mi < 2; mi++) {
#pragma unroll
            for (int hf = 0; hf < 2; hf++) {
                const int r = mi * 2 + hf;
                float mx = -1e30f;
#pragma unroll
                for (int ni = 0; ni < 8; ni++)
                    mx = fmaxf(mx, fmaxf(sc[mi][ni][hf * 2], sc[mi][ni][hf * 2 + 1]));
                mx = fmaxf(mx, __shfl_xor_sync(0xffffffffu, mx, 1));
                mx = fmaxf(mx, __shfl_xor_sync(0xffffffffu, mx, 2));
                const float newm = fmaxf(mrow[r], mx);
                const float corr = __expf(mrow[r] - newm);
                mrow[r] = newm;
                float sum = 0.0f;
#pragma unroll
                for (int ni = 0; ni < 8; ni++) {
                    const float p0 = __expf(sc[mi][ni][hf * 2]     - newm);
                    const float p1 = __expf(sc[mi][ni][hf * 2 + 1] - newm);
                    sum += p0 + p1;
                    sc[mi][ni][hf * 2]     = p0;
                    sc[mi][ni][hf * 2 + 1] = p1;
                }
                sum += __shfl_xor_sync(0xffffffffu, sum, 1);
                sum += __shfl_xor_sync(0xffffffffu, sum, 2);
                lrow[r] = lrow[r] * corr + sum;
#pragma unroll
                for (int nd = 0; nd < 8; nd++) {
                    acc[mi][nd][hf * 2]     *= corr;
                    acc[mi][nd][hf * 2 + 1] *= corr;
                }
            }
        }

        const int src0 = g * 4 + (tg >> 1);
        const int src1 = src0 + 2;
        const bool odd = tg & 1;
#pragma unroll
        for (int kt = 0; kt < 8; kt++) {
            uint32_t ap[2][4];
#pragma unroll
            for (int mi = 0; mi < 2; mi++) {
                const float c0 = sc[mi][kt][0], c1 = sc[mi][kt][1];
                const float c2 = sc[mi][kt][2], c3 = sc[mi][kt][3];
                const float v00 = __shfl_sync(0xffffffffu, c0, src0);
                const float v01 = __shfl_sync(0xffffffffu, c1, src0);
                const float v10 = __shfl_sync(0xffffffffu, c0, src1);
                const float v11 = __shfl_sync(0xffffffffu, c1, src1);
                const float v20 = __shfl_sync(0xffffffffu, c2, src0);
                const float v21 = __shfl_sync(0xffffffffu, c3, src0);
                const float v30 = __shfl_sync(0xffffffffu, c2, src1);
                const float v31 = __shfl_sync(0xffffffffu, c3, src1);
                ap[mi][0] = __float_as_uint(tf32r(odd ? v01 : v00));
                ap[mi][1] = __float_as_uint(tf32r(odd ? v21 : v20));
                ap[mi][2] = __float_as_uint(tf32r(odd ? v11 : v10));
                ap[mi][3] = __float_as_uint(tf32r(odd ? v31 : v30));
            }
            uint32_t bv[8][2];
#pragma unroll
            for (int nd = 0; nd < 8; nd++) {
                const uint32_t* bp = Vs + (nd * 8 + g) * ATT_PAD + kt * 8 + tg;
                bv[nd][0] = bp[0];
                bv[nd][1] = bp[4];
            }
#pragma unroll
            for (int mi = 0; mi < 2; mi++)
#pragma unroll
                for (int nd = 0; nd < 8; nd++)
                    mma_tf32(acc[mi][nd], ap[mi], bv[nd]);
        }
        __syncthreads();
    }

    const int b = bh >> 4, h = bh & 15;
#pragma unroll
    for (int mi = 0; mi < 2; mi++) {
        const int row0 = q0 + wid * 32 + mi * 16 + g;
        const float inv0 = 1.0f / lrow[mi * 2 + 0];
        const float inv1 = 1.0f / lrow[mi * 2 + 1];
#pragma unroll
        for (int nd = 0; nd < 8; nd++) {
            const int col = h * 64 + nd * 8 + tg * 2;
            float2 o0, o1;
            o0.x = acc[mi][nd][0] * inv0; o0.y = acc[mi][nd][1] * inv0;
            o1.x = acc[mi][nd][2] * inv1; o1.y = acc[mi][nd][3] * inv1;
            *(float2*)(g_attn + ((size_t)(b * SS + row0)) * DD + col) = o0;
            *(float2*)(g_attn + ((size_t)(b * SS + row0 + 8)) * DD + col) = o1;
        }
    }
}

// ---------------------------------------------------------------------------
// LayerNorm; writes fp32 g_ln (residual) and tf32-rounded g_lnr (GEMM A)
// ---------------------------------------------------------------------------
__global__ __launch_bounds__(256) void ln_kernel(
    const float* __restrict__ gw, const float* __restrict__ bw)
{
    __shared__ float red[64];
    const int r = blockIdx.x;
    const int t = threadIdx.x;

    const float4 x = ((const float4*)(g_attn + (size_t)r * DD))[t];
    float s  = x.x + x.y + x.z + x.w;
    float ss = x.x*x.x + x.y*x.y + x.z*x.z + x.w*x.w;
#pragma unroll
    for (int o = 16; o > 0; o >>= 1) {
        s  += __shfl_xor_sync(0xffffffffu, s,  o);
        ss += __shfl_xor_sync(0xffffffffu, ss, o);
    }
    if ((t & 31) == 0) { red[t >> 5] = s; red[32 + (t >> 5)] = ss; }
    __syncthreads();
    if (t == 0) {
        float S = 0, SSum = 0;
#pragma unroll
        for (int i = 0; i < 8; i++) { S += red[i]; SSum += red[32 + i]; }
        red[0] = S; red[32] = SSum;
    }
    __syncthreads();
    const float mu  = red[0]  * (1.0f / DD);
    const float var = red[32] * (1.0f / DD) - mu * mu;
    const float inv = rsqrtf(var + 1e-5f);

    const int c = t * 4;
    float4 o;
    o.x = (x.x - mu) * inv * gw[c + 0] + bw[c + 0];
    o.y = (x.y - mu) * inv * gw[c + 1] + bw[c + 1];
    o.z = (x.z - mu) * inv * gw[c + 2] + bw[c + 2];
    o.w = (x.w - mu) * inv * gw[c + 3] + bw[c + 3];
    ((float4*)(g_ln + (size_t)r * DD))[t] = o;
    float4 orr;
    orr.x = tf32r(o.x); orr.y = tf32r(o.y); orr.z = tf32r(o.z); orr.w = tf32r(o.w);
    ((float4*)(g_lnr + (size_t)r * DD))[t] = orr;
}

// ---------------------------------------------------------------------------
extern "C" void kernel_launch(void* const* d_in, const int* in_sizes, int n_in,
                              void* d_out, int out_size)
{
    const float* q       = (const float*)d_in[0];
    const float* Wqkv    = (const float*)d_in[3];
    const float* bqkv    = (const float*)d_in[4];
    const float* q_scale = (const float*)d_in[5];
    const float* k_scale = (const float*)d_in[6];
    const float* ln_g    = (const float*)d_in[7];
    const float* ln_b    = (const float*)d_in[8];
    const float* W1      = (const float*)d_in[9];
    const float* b1      = (const float*)d_in[10];
    const float* W2      = (const float*)d_in[11];
    const float* b2      = (const float*)d_in[12];
    float* out = (float*)d_out;

    float *p_aq, *p_ln, *p_lnr, *p_gate, *p_wqkvT, *p_w1T, *p_w2T, *p_pb1;
    cudaGetSymbolAddress((void**)&p_aq,    g_aq);
    cudaGetSymbolAddress((void**)&p_ln,    g_ln);
    cudaGetSymbolAddress((void**)&p_lnr,   g_lnr);
    cudaGetSymbolAddress((void**)&p_gate,  g_gate);
    cudaGetSymbolAddress((void**)&p_wqkvT, g_wqkvT);
    cudaGetSymbolAddress((void**)&p_w1T,   g_w1T);
    cudaGetSymbolAddress((void**)&p_w2T,   g_w2T);
    cudaGetSymbolAddress((void**)&p_pb1,   g_pb1);

    const int GSMEM = STAGE_F * 2 * 4;                    // 73728 bytes
    const int ASMEM = (ATT_QF + 2 * ATT_STF) * 4;         // 104448 bytes
    cudaFuncSetAttribute(gemm_mma_kernel<0>, cudaFuncAttributeMaxDynamicSharedMemorySize, GSMEM);
    cudaFuncSetAttribute(gemm_mma_kernel<1>, cudaFuncAttributeMaxDynamicSharedMemorySize, GSMEM);
    cudaFuncSetAttribute(gemm_mma_kernel<2>, cudaFuncAttributeMaxDynamicSharedMemorySize, GSMEM);
    cudaFuncSetAttribute(attn_mma_kernel, cudaFuncAttributeMaxDynamicSharedMemorySize, ASMEM);

    // 0-2: prep (QKV GEMM becomes launch index 3 -> ncu -s 5 capture slot)
    transpose_round_kernel<0><<<dim3(N_QKV / 32, DD / 32), dim3(32, 8)>>>(Wqkv, p_wqkvT, DD, N_QKV);
    round_copy_kernel<<<ROWS * DD / 4 / 256, 256>>>(q, p_aq);
    transpose_round_kernel<1><<<dim3(FF_IN / 32, DD / 32), dim3(32, 8)>>>(W1, p_w1T, DD, FF_IN);

    // 3: QKV projection + fused l2norm/scale/RoPE/V-transpose epilogue
    gemm_mma_kernel<2><<<dim3(N_QKV / GBN, ROWS / GBM), 256, GSMEM>>>(
        p_aq, p_wqkvT, bqkv, nullptr, q_scale, k_scale, nullptr, N_QKV, DD);

    // 4-5: remaining prep
    transpose_round_kernel<0><<<dim3(DD / 32, FF_HID / 32), dim3(32, 8)>>>(W2, p_w2T, FF_HID, DD);
    permute_b1_kernel<<<FF_HID / 256, 256>>>(b1);

    // 6: attention (tensor cores)
    attn_mma_kernel<<<dim3(BB * HH, SS / 128), 128, ASMEM>>>();

    // 7: LayerNorm
    ln_kernel<<<ROWS, 256>>>(ln_g, ln_b);

    // 8: FF1 + fused SwiGLU, writes g_gate
    gemm_mma_kernel<1><<<dim3(FF_IN / GBN, ROWS / GBM), 256, GSMEM>>>(
        p_lnr, p_w1T, p_pb1, nullptr, nullptr, nullptr, p_gate, FF_IN, DD);

    // 9: FF2 + bias + residual(ln)
    gemm_mma_kernel<0><<<dim3(DD / GBN, ROWS / GBM), 256, GSMEM>>>(
        p_gate, p_w2T, b2, p_ln, nullptr, nullptr, out, DD, FF_HID);
}

// round 16
// speedup vs baseline: 1.6144x; 1.0267x over previous
#include <cuda_runtime.h>
#include <math.h>
#include <stdint.h>

// Problem constants
#define BB 4
#define SS 2048
#define HH 16
#define DH 64
#define DD 1024            // H*DH
#define ROWS (BB*SS)       // 8192
#define N_QKV (3*DD)       // 3072
#define FF_IN 4096
#define FF_HID 2048

// Scratch (device globals; no allocation)
__device__ float g_aq  [(size_t)ROWS * DD];      // tf32-rounded q input
__device__ float g_q   [(size_t)ROWS * DD];      // [B*H, S, 64] tf32, pre-scaled 0.125
__device__ float g_k   [(size_t)ROWS * DD];      // [B*H, S, 64] tf32
__device__ float g_vT  [(size_t)ROWS * DD];      // [B*H, 64, S] tf32
__device__ float g_attn[(size_t)ROWS * DD];      // [B*S, 1024]
__device__ float g_ln  [(size_t)ROWS * DD];      // LN out (fp32, residual)
__device__ float g_lnr [(size_t)ROWS * DD];      // LN out tf32-rounded (GEMM A)
__device__ float g_gate[(size_t)ROWS * FF_HID];  // [B*S, 2048] tf32-rounded
__device__ float g_wqkvT[(size_t)N_QKV * DD];    // [3072, 1024]
__device__ float g_w1T  [(size_t)FF_IN * DD];    // [4096, 1024] x/gate interleaved
__device__ float g_w2T  [(size_t)DD * FF_HID];   // [1024, 2048]
__device__ float g_pb1  [FF_IN];                 // permuted b1

// ---------------------------------------------------------------------------
// helpers
// ---------------------------------------------------------------------------
__device__ __forceinline__ float tf32r(float x) {
    float o; asm("cvt.rna.tf32.f32 %0, %1;" : "=f"(o) : "f"(x)); return o;
}
__device__ __forceinline__ uint32_t smem_u32(const void* p) {
    uint32_t a;
    asm("{ .reg .u64 t; cvta.to.shared.u64 t, %1; cvt.u32.u64 %0, t; }" : "=r"(a) : "l"(p));
    return a;
}
__device__ __forceinline__ void cpasync16(uint32_t dst, const void* src) {
    asm volatile("cp.async.cg.shared.global [%0], [%1], 16;" :: "r"(dst), "l"(src) : "memory");
}
__device__ __forceinline__ void cp_commit() {
    asm volatile("cp.async.commit_group;" ::: "memory");
}
__device__ __forceinline__ void cp_wait1() {
    asm volatile("cp.async.wait_group 1;" ::: "memory");
}
__device__ __forceinline__ void cp_wait0() {
    asm volatile("cp.async.wait_group 0;" ::: "memory");
}
__device__ __forceinline__ void mma_tf32(float* c, const uint32_t* a, const uint32_t* b) {
    asm volatile(
        "mma.sync.aligned.m16n8k8.row.col.f32.tf32.tf32.f32 "
        "{%0,%1,%2,%3}, {%4,%5,%6,%7}, {%8,%9}, {%0,%1,%2,%3};"
        : "+f"(c[0]), "+f"(c[1]), "+f"(c[2]), "+f"(c[3])
        : "r"(a[0]), "r"(a[1]), "r"(a[2]), "r"(a[3]), "r"(b[0]), "r"(b[1]));
}
__device__ __forceinline__ void ldsm4(uint32_t* r, uint32_t addr) {
    asm volatile("ldmatrix.sync.aligned.m8n8.x4.shared.b16 {%0,%1,%2,%3}, [%4];"
        : "=r"(r[0]), "=r"(r[1]), "=r"(r[2]), "=r"(r[3]) : "r"(addr));
}

// ---------------------------------------------------------------------------
// tf32 mma.sync GEMM: C[M,N] = A[M,K] @ Bt[N,K]^T + bias (+ res)
// MODE 0: plain (+res).   MODE 1: fused SwiGLU (interleaved x/gate cols).
// MODE 2: fused QKV epilogue (l2norm+scale+RoPE for q/k, transposed V store).
// 3-stage cp.async pipeline, 1 barrier/iter, ldmatrix fragment loads.
// ---------------------------------------------------------------------------
#define GBM 128
#define GBN 128
#define GBK 32
#define APAD 36
#define STAGE_F (2 * 128 * APAD)   // floats per stage (A+B)
#define NSTAGE 3

template<int MODE>
__global__ __launch_bounds__(256) void gemm_mma_kernel(
    const float* __restrict__ A, const float* __restrict__ Bt,
    const float* __restrict__ bias, const float* __restrict__ res,
    const float* __restrict__ qsc, const float* __restrict__ ksc,
    float* __restrict__ C, int N, int K)
{
    extern __shared__ float sm[];
    const int tid = threadIdx.x;
    const int wid = tid >> 5, lane = tid & 31;
    const int g = lane >> 2, tg = lane & 3;
    const int warp_m = wid & 3, warp_n = wid >> 2;
    const int m0 = blockIdx.y * GBM, n0 = blockIdx.x * GBN;
    const uint32_t smbase = smem_u32(sm);

    float acc[2][8][4] = {};

    const int NIT = K >> 5;

    auto load_stage = [&](int it, int s) {
        const int k0 = it * GBK;
        const uint32_t aB = smbase + (uint32_t)s * STAGE_F * 4;
        const uint32_t bB = aB + 128 * APAD * 4;
#pragma unroll
        for (int i = 0; i < 4; i++) {
            const int idx = tid + 256 * i;
            const int row = idx >> 3, c4 = (idx & 7) * 4;
            cpasync16(aB + (uint32_t)(row * APAD + c4) * 4,
                      A  + (size_t)(m0 + row) * K + k0 + c4);
            cpasync16(bB + (uint32_t)(row * APAD + c4) * 4,
                      Bt + (size_t)(n0 + row) * K + k0 + c4);
        }
        cp_commit();
    };

    // ldmatrix lane-address components (byte offsets within stage)
    const int lane15 = lane & 15;              // A: row within 16-row tile
    const uint32_t aoff = ((lane >> 4) & 1) * 16;   // A: 16B half-row select
    const int brow  = lane & 7;                // B: row within 8-row tile
    const int bsel  = (lane >> 4) & 1;         // B: which tile of the pair
    const uint32_t boff = ((lane >> 3) & 1) * 16;   // B: 16B half-row select

    // per-thread invariant address parts (relative to stage base, bytes)
    const uint32_t aAdr0 = (uint32_t)((warp_m * 32 + 0  + lane15) * APAD) * 4 + aoff;
    const uint32_t aAdr1 = (uint32_t)((warp_m * 32 + 16 + lane15) * APAD) * 4 + aoff;
    uint32_t bAdr[4];
#pragma unroll
    for (int p = 0; p < 4; p++)
        bAdr[p] = (uint32_t)(128 * APAD + (warp_n * 64 + (2 * p + bsel) * 8 + brow) * APAD) * 4 + boff;

    load_stage(0, 0);
    load_stage(1, 1);

    for (int it = 0; it < NIT; it++) {
        const int s = it % NSTAGE;
        if (it + 1 < NIT) cp_wait1(); else cp_wait0();
        __syncthreads();
        if (it + 2 < NIT) load_stage(it + 2, (it + 2) % NSTAGE);

        const uint32_t stg = smbase + (uint32_t)s * STAGE_F * 4;

#pragma unroll
        for (int kt = 0; kt < 4; kt++) {
            const uint32_t ko = kt * 32;   // 8 floats = 32 bytes
            uint32_t a[2][4], bb[4][4];
            ldsm4(a[0], stg + aAdr0 + ko);
            ldsm4(a[1], stg + aAdr1 + ko);
#pragma unroll
            for (int p = 0; p < 4; p++)
                ldsm4(bb[p], stg + bAdr[p] + ko);
#pragma unroll
            for (int mi = 0; mi < 2; mi++)
#pragma unroll
                for (int ni = 0; ni < 8; ni++)
                    mma_tf32(acc[mi][ni], a[mi], &bb[ni >> 1][(ni & 1) * 2]);
        }
    }

    if (MODE == 2) {
        // --- fused QKV epilogue ---
        const int segcol = n0 + warp_n * 64;          // multiple of 64
        const int h   = segcol / 192;                 // head
        const int seg = (segcol >> 6) % 3;            // 0=q, 1=k, 2=v
#pragma unroll
        for (int mi = 0; mi < 2; mi++) {
#pragma unroll
            for (int hf = 0; hf < 2; hf++) {
                const int row  = m0 + warp_m * 32 + mi * 16 + g + hf * 8;  // b*S+s
                const int b    = row >> 11;
                const int spos = row & (SS - 1);
                float v[8][2];
#pragma unroll
                for (int ni = 0; ni < 8; ni++) {
#pragma unroll
                    for (int c = 0; c < 2; c++)
                        v[ni][c] = acc[mi][ni][hf * 2 + c] + bias[segcol + ni * 8 + tg * 2 + c];
                }
                if (seg == 2) {
                    // V: transposed store to g_vT[bh][d][s]
                    float* dst = g_vT + ((size_t)(b * HH + h) * DH) * SS + spos;
#pragma unroll
                    for (int ni = 0; ni < 8; ni++) {
#pragma unroll
                        for (int c = 0; c < 2; c++)
                            dst[(size_t)(ni * 8 + tg * 2 + c) * SS] = tf32r(v[ni][c]);
                    }
                } else {
                    // l2norm over the 64 dims (quad reduction)
                    float ssum = 0.0f;
#pragma unroll
                    for (int ni = 0; ni < 8; ni++)
                        ssum += v[ni][0] * v[ni][0] + v[ni][1] * v[ni][1];
                    ssum += __shfl_xor_sync(0xffffffffu, ssum, 1);
                    ssum += __shfl_xor_sync(0xffffffffu, ssum, 2);
                    const float inv = 1.0f / fmaxf(sqrtf(ssum), 1e-12f);
                    const float* sv = seg ? ksc : qsc;
#pragma unroll
                    for (int ni = 0; ni < 8; ni++) {
#pragma unroll
                        for (int c = 0; c < 2; c++)
                            v[ni][c] *= inv * sv[ni * 8 + tg * 2 + c];
                    }
                    // xpos-RoPE: pairs (d, d+32) = (ni, ni+4) same lane
                    const float power = ((float)spos - 1024.0f) * (1.0f / 512.0f);
                    float outv[8][2];
#pragma unroll
                    for (int ni = 0; ni < 4; ni++) {
#pragma unroll
                        for (int c = 0; c < 2; c++) {
                            const int j = ni * 8 + tg * 2 + c;
                            const float invf = __expf(-(float)j * 0.28782313662425574f);
                            float sn, cs;
                            __sincosf((float)spos * invf, &sn, &cs);
                            float sc = __powf((2.0f * j + 25.6f) * (1.0f / 89.6f), power);
                            if (seg == 1) sc = 1.0f / sc;
                            outv[ni][c]     = (v[ni][c] * cs - v[ni + 4][c] * sn) * sc;
                            outv[ni + 4][c] = (v[ni + 4][c] * cs + v[ni][c] * sn) * sc;
                        }
                    }
                    const float mul = seg ? 1.0f : 0.125f;   // fold softmax scale into q
                    float* dst = (seg ? g_k : g_q) + ((size_t)((b * HH + h) * SS + spos)) * DH;
#pragma unroll
                    for (int ni = 0; ni < 8; ni++) {
                        float2 w;
                        w.x = tf32r(outv[ni][0] * mul);
                        w.y = tf32r(outv[ni][1] * mul);
                        *(float2*)(dst + ni * 8 + tg * 2) = w;
                    }
                }
            }
        }
    } else if (MODE == 1) {
        // cols (even, odd) = (x, gate); out[col/2] = silu(gate)*x, C is [M, N/2]
        const int NH = N >> 1;
#pragma unroll
        for (int mi = 0; mi < 2; mi++) {
            const int row0 = m0 + warp_m * 32 + mi * 16 + g;
#pragma unroll
            for (int ni = 0; ni < 8; ni++) {
                const int col = n0 + warp_n * 64 + ni * 8 + tg * 2;
                const float2 bv = *(const float2*)(bias + col);
                const float x0 = acc[mi][ni][0] + bv.x;
                const float g0 = acc[mi][ni][1] + bv.y;
                const float x1 = acc[mi][ni][2] + bv.x;
                const float g1 = acc[mi][ni][3] + bv.y;
                const float o0 = tf32r(x0 * g0 * __frcp_rn(1.0f + __expf(-g0)));
                const float o1 = tf32r(x1 * g1 * __frcp_rn(1.0f + __expf(-g1)));
                const float p0 = __shfl_xor_sync(0xffffffffu, o0, 1);
                const float p1 = __shfl_xor_sync(0xffffffffu, o1, 1);
                const int cp = col >> 1;
                if ((tg & 1) == 0) {
                    *(float2*)(C + (size_t)row0 * NH + cp) = make_float2(o0, p0);
                } else {
                    *(float2*)(C + (size_t)(row0 + 8) * NH + cp - 1) = make_float2(p1, o1);
                }
            }
        }
    } else {
#pragma unroll
        for (int mi = 0; mi < 2; mi++) {
            const int row0 = m0 + warp_m * 32 + mi * 16 + g;
#pragma unroll
            for (int ni = 0; ni < 8; ni++) {
                const int col = n0 + warp_n * 64 + ni * 8 + tg * 2;
                const float2 bv = *(const float2*)(bias + col);
                float2 o0, o1;
                o0.x = acc[mi][ni][0] + bv.x;
                o0.y = acc[mi][ni][1] + bv.y;
                o1.x = acc[mi][ni][2] + bv.x;
                o1.y = acc[mi][ni][3] + bv.y;
                if (res) {
                    const float2 r0 = *(const float2*)(res + (size_t)row0 * N + col);
                    const float2 r1 = *(const float2*)(res + (size_t)(row0 + 8) * N + col);
                    o0.x += r0.x; o0.y += r0.y; o1.x += r1.x; o1.y += r1.y;
                }
                *(float2*)(C + (size_t)row0 * N + col) = o0;
                *(float2*)(C + (size_t)(row0 + 8) * N + col) = o1;
            }
        }
    }
}

// ---------------------------------------------------------------------------
// Transpose + tf32-round: out[c*R + r] = rnd(in[r*Cc + c])
// PERM=1: output row index remapped for x/gate interleave (Cc=4096 case)
// ---------------------------------------------------------------------------
template<int PERM>
__global__ __launch_bounds__(256) void transpose_round_kernel(
    const float* __restrict__ in, float* __restrict__ out, int R, int Cc)
{
    __shared__ float t[32][33];
    const int bx = blockIdx.x, by = blockIdx.y;
    const int tx = threadIdx.x, ty = threadIdx.y;
#pragma unroll
    for (int i = 0; i < 32; i += 8)
        t[ty + i][tx] = in[(size_t)(by * 32 + ty + i) * Cc + bx * 32 + tx];
    __syncthreads();
#pragma unroll
    for (int i = 0; i < 32; i += 8) {
        int r = bx * 32 + ty + i;
        if (PERM) r = (r < 2048) ? (2 * r) : (2 * (r - 2048) + 1);
        out[(size_t)r * R + by * 32 + tx] = tf32r(t[tx][ty + i]);
    }
}

// permute b1: out[2c]=b1[c], out[2c+1]=b1[2048+c]
__global__ __launch_bounds__(256) void permute_b1_kernel(const float* __restrict__ b1)
{
    const int c = blockIdx.x * 256 + threadIdx.x;   // 0..2047
    g_pb1[2 * c]     = b1[c];
    g_pb1[2 * c + 1] = b1[FF_HID + c];
}

__global__ __launch_bounds__(256) void round_copy_kernel(
    const float* __restrict__ in, float* __restrict__ out)
{
    const int i = blockIdx.x * 256 + threadIdx.x;
    float4 v = ((const float4*)in)[i];
    v.x = tf32r(v.x); v.y = tf32r(v.y); v.z = tf32r(v.z); v.w = tf32r(v.w);
    ((float4*)out)[i] = v;
}

// ---------------------------------------------------------------------------
// Flash attention via mma.sync tf32. (unchanged this round)
// ---------------------------------------------------------------------------
#define ATT_PAD 68
#define ATT_QF   (128 * ATT_PAD)           // Q floats
#define ATT_STF  (2 * 64 * ATT_PAD)        // per-stage floats (K + V^T)

__global__ __launch_bounds__(128) void attn_mma_kernel()
{
    extern __shared__ float sm[];
    float* Qs = sm;
    float* Stg = sm + ATT_QF;

    const int bh = blockIdx.x;
    const int q0 = blockIdx.y * 128;
    const int tid = threadIdx.x, wid = tid >> 5, lane = tid & 31;
    const int g = lane >> 2, tg = lane & 3;
    const uint32_t smbase = smem_u32(sm);

    const float* Q  = g_q + ((size_t)bh * SS + q0) * DH;
    const float* K  = g_k + (size_t)bh * SS * DH;
    const float* Vt = g_vT + (size_t)bh * DH * SS;

    for (int i = tid; i < 128 * 16; i += 128) {
        const int r = i >> 4, c4 = (i & 15) * 4;
        *(float4*)(&Qs[r * ATT_PAD + c4]) = *(const float4*)(Q + r * DH + c4);
    }

    auto load_kv = [&](int t, int s) {
        const uint32_t kB = smbase + (ATT_QF + s * ATT_STF) * 4;
        const uint32_t vB = kB + 64 * ATT_PAD * 4;
        const float* Kg = K + (size_t)t * 64 * DH;
#pragma unroll
        for (int i = 0; i < 8; i++) {
            const int idx = tid + 128 * i;
            const int r = idx >> 4, c4 = (idx & 15) * 4;
            cpasync16(kB + (uint32_t)(r * ATT_PAD + c4) * 4, Kg + r * DH + c4);
            cpasync16(vB + (uint32_t)(r * ATT_PAD + c4) * 4, Vt + (size_t)r * SS + t * 64 + c4);
        }
        cp_commit();
    };

    load_kv(0, 0);

    float acc[2][8][4] = {};
    float mrow[4] = {-1e30f, -1e30f, -1e30f, -1e30f};
    float lrow[4] = {};

    const int NT = SS / 64;
    for (int t = 0; t < NT; t++) {
        const int s = t & 1;
        if (t + 1 < NT) load_kv(t + 1, s ^ 1);
        if (t + 1 < NT) cp_wait1(); else cp_wait0();
        __syncthreads();

        const uint32_t* Ks = (const uint32_t*)(Stg + s * ATT_STF);
        const uint32_t* Vs = Ks + 64 * ATT_PAD;

        float sc[2][8][4] = {};
#pragma unroll
        for (int kt = 0; kt < 8; kt++) {
            uint32_t aq[2][4], bk[8][2];
#pragma unroll
            for (int mi = 0; mi < 2; mi++) {
                const uint32_t* ap = (const uint32_t*)Qs + (wid * 32 + mi * 16 + g) * ATT_PAD + kt * 8 + tg;
                aq[mi][0] = ap[0];
                aq[mi][1] = ap[8 * ATT_PAD];
                aq[mi][2] = ap[4];
                aq[mi][3] = ap[8 * ATT_PAD + 4];
            }
#pragma unroll
            for (int ni = 0; ni < 8; ni++) {
                const uint32_t* bp = Ks + (ni * 8 + g) * ATT_PAD + kt * 8 + tg;
                bk[ni][0] = bp[0];
                bk[ni][1] = bp[4];
            }
#pragma unroll
            for (int mi = 0; mi < 2; mi++)
#pragma unroll
                for (int ni = 0; ni < 8; ni++)
                    mma_tf32(sc[mi][ni], aq[mi], bk[ni]);
        }

#pragma unroll
        for (int mi = 0; mi < 2; mi++) {
#pragma unroll
            for (int hf = 0; hf < 2; hf++) {
                const int r = mi * 2 + hf;
                float mx = -1e30f;
#pragma unroll
                for (int ni = 0; ni < 8; ni++)
                    mx = fmaxf(mx, fmaxf(sc[mi][ni][hf * 2], sc[mi][ni][hf * 2 + 1]));
                mx = fmaxf(mx, __shfl_xor_sync(0xffffffffu, mx, 1));
                mx = fmaxf(mx, __shfl_xor_sync(0xffffffffu, mx, 2));
                const float newm = fmaxf(mrow[r], mx);
                const float corr = __expf(mrow[r] - newm);
                mrow[r] = newm;
                float sum = 0.0f;
#pragma unroll
                for (int ni = 0; ni < 8; ni++) {
                    const float p0 = __expf(sc[mi][ni][hf * 2]     - newm);
                    const float p1 = __expf(sc[mi][ni][hf * 2 + 1] - newm);
                    sum += p0 + p1;
                    sc[mi][ni][hf * 2]     = p0;
                    sc[mi][ni][hf * 2 + 1] = p1;
                }
                sum += __shfl_xor_sync(0xffffffffu, sum, 1);
                sum += __shfl_xor_sync(0xffffffffu, sum, 2);
                lrow[r] = lrow[r] * corr + sum;
#pragma unroll
                for (int nd = 0; nd < 8; nd++) {
                    acc[mi][nd][hf * 2]     *= corr;
                    acc[mi][nd][hf * 2 + 1] *= corr;
                }
            }
        }

        const int src0 = g * 4 + (tg >> 1);
        const int src1 = src0 + 2;
        const bool odd = tg & 1;
#pragma unroll
        for (int kt = 0; kt < 8; kt++) {
            uint32_t ap[2][4];
#pragma unroll
            for (int mi = 0; mi < 2; mi++) {
                const float c0 = sc[mi][kt][0], c1 = sc[mi][kt][1];
                const float c2 = sc[mi][kt][2], c3 = sc[mi][kt][3];
                const float v00 = __shfl_sync(0xffffffffu, c0, src0);
                const float v01 = __shfl_sync(0xffffffffu, c1, src0);
                const float v10 = __shfl_sync(0xffffffffu, c0, src1);
                const float v11 = __shfl_sync(0xffffffffu, c1, src1);
                const float v20 = __shfl_sync(0xffffffffu, c2, src0);
                const float v21 = __shfl_sync(0xffffffffu, c3, src0);
                const float v30 = __shfl_sync(0xffffffffu, c2, src1);
                const float v31 = __shfl_sync(0xffffffffu, c3, src1);
                ap[mi][0] = __float_as_uint(tf32r(odd ? v01 : v00));
                ap[mi][1] = __float_as_uint(tf32r(odd ? v21 : v20));
                ap[mi][2] = __float_as_uint(tf32r(odd ? v11 : v10));
                ap[mi][3] = __float_as_uint(tf32r(odd ? v31 : v30));
            }
            uint32_t bv[8][2];
#pragma unroll
            for (int nd = 0; nd < 8; nd++) {
                const uint32_t* bp = Vs + (nd * 8 + g) * ATT_PAD + kt * 8 + tg;
                bv[nd][0] = bp[0];
                bv[nd][1] = bp[4];
            }
#pragma unroll
            for (int mi = 0; mi < 2; mi++)
#pragma unroll
                for (int nd = 0; nd < 8; nd++)
                    mma_tf32(acc[mi][nd], ap[mi], bv[nd]);
        }
        __syncthreads();
    }

    const int b = bh >> 4, h = bh & 15;
#pragma unroll
    for (int mi = 0; mi < 2; mi++) {
        const int row0 = q0 + wid * 32 + mi * 16 + g;
        const float inv0 = 1.0f / lrow[mi * 2 + 0];
        const float inv1 = 1.0f / lrow[mi * 2 + 1];
#pragma unroll
        for (int nd = 0; nd < 8; nd++) {
            const int col = h * 64 + nd * 8 + tg * 2;
            float2 o0, o1;
            o0.x = acc[mi][nd][0] * inv0; o0.y = acc[mi][nd][1] * inv0;
            o1.x = acc[mi][nd][2] * inv1; o1.y = acc[mi][nd][3] * inv1;
            *(float2*)(g_attn + ((size_t)(b * SS + row0)) * DD + col) = o0;
            *(float2*)(g_attn + ((size_t)(b * SS + row0 + 8)) * DD + col) = o1;
        }
    }
}

// ---------------------------------------------------------------------------
// LayerNorm; writes fp32 g_ln (residual) and tf32-rounded g_lnr (GEMM A)
// ---------------------------------------------------------------------------
__global__ __launch_bounds__(256) void ln_kernel(
    const float* __restrict__ gw, const float* __restrict__ bw)
{
    __shared__ float red[64];
    const int r = blockIdx.x;
    const int t = threadIdx.x;

    const float4 x = ((const float4*)(g_attn + (size_t)r * DD))[t];
    float s  = x.x + x.y + x.z + x.w;
    float ss = x.x*x.x + x.y*x.y + x.z*x.z + x.w*x.w;
#pragma unroll
    for (int o = 16; o > 0; o >>= 1) {
        s  += __shfl_xor_sync(0xffffffffu, s,  o);
        ss += __shfl_xor_sync(0xffffffffu, ss, o);
    }
    if ((t & 31) == 0) { red[t >> 5] = s; red[32 + (t >> 5)] = ss; }
    __syncthreads();
    if (t == 0) {
        float S = 0, SSum = 0;
#pragma unroll
        for (int i = 0; i < 8; i++) { S += red[i]; SSum += red[32 + i]; }
        red[0] = S; red[32] = SSum;
    }
    __syncthreads();
    const float mu  = red[0]  * (1.0f / DD);
    const float var = red[32] * (1.0f / DD) - mu * mu;
    const float inv = rsqrtf(var + 1e-5f);

    const int c = t * 4;
    float4 o;
    o.x = (x.x - mu) * inv * gw[c + 0] + bw[c + 0];
    o.y = (x.y - mu) * inv * gw[c + 1] + bw[c + 1];
    o.z = (x.z - mu) * inv * gw[c + 2] + bw[c + 2];
    o.w = (x.w - mu) * inv * gw[c + 3] + bw[c + 3];
    ((float4*)(g_ln + (size_t)r * DD))[t] = o;
    float4 orr;
    orr.x = tf32r(o.x); orr.y = tf32r(o.y); orr.z = tf32r(o.z); orr.w = tf32r(o.w);
    ((float4*)(g_lnr + (size_t)r * DD))[t] = orr;
}

// ---------------------------------------------------------------------------
extern "C" void kernel_launch(void* const* d_in, const int* in_sizes, int n_in,
                              void* d_out, int out_size)
{
    const float* q       = (const float*)d_in[0];
    const float* Wqkv    = (const float*)d_in[3];
    const float* bqkv    = (const float*)d_in[4];
    const float* q_scale = (const float*)d_in[5];
    const float* k_scale = (const float*)d_in[6];
    const float* ln_g    = (const float*)d_in[7];
    const float* ln_b    = (const float*)d_in[8];
    const float* W1      = (const float*)d_in[9];
    const float* b1      = (const float*)d_in[10];
    const float* W2      = (const float*)d_in[11];
    const float* b2      = (const float*)d_in[12];
    float* out = (float*)d_out;

    float *p_aq, *p_ln, *p_lnr, *p_gate, *p_wqkvT, *p_w1T, *p_w2T, *p_pb1;
    cudaGetSymbolAddress((void**)&p_aq,    g_aq);
    cudaGetSymbolAddress((void**)&p_ln,    g_ln);
    cudaGetSymbolAddress((void**)&p_lnr,   g_lnr);
    cudaGetSymbolAddress((void**)&p_gate,  g_gate);
    cudaGetSymbolAddress((void**)&p_wqkvT, g_wqkvT);
    cudaGetSymbolAddress((void**)&p_w1T,   g_w1T);
    cudaGetSymbolAddress((void**)&p_w2T,   g_w2T);
    cudaGetSymbolAddress((void**)&p_pb1,   g_pb1);

    const int GSMEM = STAGE_F * NSTAGE * 4;               // 110592 bytes
    const int ASMEM = (ATT_QF + 2 * ATT_STF) * 4;         // 104448 bytes
    cudaFuncSetAttribute(gemm_mma_kernel<0>, cudaFuncAttributeMaxDynamicSharedMemorySize, GSMEM);
    cudaFuncSetAttribute(gemm_mma_kernel<1>, cudaFuncAttributeMaxDynamicSharedMemorySize, GSMEM);
    cudaFuncSetAttribute(gemm_mma_kernel<2>, cudaFuncAttributeMaxDynamicSharedMemorySize, GSMEM);
    cudaFuncSetAttribute(attn_mma_kernel, cudaFuncAttributeMaxDynamicSharedMemorySize, ASMEM);

    // 0-2: prep (QKV GEMM stays at launch index 3 -> ncu capture slot)
    transpose_round_kernel<0><<<dim3(N_QKV / 32, DD / 32), dim3(32, 8)>>>(Wqkv, p_wqkvT, DD, N_QKV);
    round_copy_kernel<<<ROWS * DD / 4 / 256, 256>>>(q, p_aq);
    transpose_round_kernel<1><<<dim3(FF_IN / 32, DD / 32), dim3(32, 8)>>>(W1, p_w1T, DD, FF_IN);

    // 3: QKV projection + fused l2norm/scale/RoPE/V-transpose epilogue
    gemm_mma_kernel<2><<<dim3(N_QKV / GBN, ROWS / GBM), 256, GSMEM>>>(
        p_aq, p_wqkvT, bqkv, nullptr, q_scale, k_scale, nullptr, N_QKV, DD);

    // 4-5: remaining prep
    transpose_round_kernel<0><<<dim3(DD / 32, FF_HID / 32), dim3(32, 8)>>>(W2, p_w2T, FF_HID, DD);
    permute_b1_kernel<<<FF_HID / 256, 256>>>(b1);

    // 6: attention (tensor cores)
    attn_mma_kernel<<<dim3(BB * HH, SS / 128), 128, ASMEM>>>();

    // 7: LayerNorm
    ln_kernel<<<ROWS, 256>>>(ln_g, ln_b);

    // 8: FF1 + fused SwiGLU, writes g_gate
    gemm_mma_kernel<1><<<dim3(FF_IN / GBN, ROWS / GBM), 256, GSMEM>>>(
        p_lnr, p_w1T, p_pb1, nullptr, nullptr, nullptr, p_gate, FF_IN, DD);

    // 9: FF2 + bias + residual(ln)
    gemm_mma_kernel<0><<<dim3(DD / GBN, ROWS / GBM), 256, GSMEM>>>(
        p_gate, p_w2T, b2, p_ln, nullptr, nullptr, out, DD, FF_HID);
}

// round 17
// speedup vs baseline: 1.6197x; 1.0033x over previous
#include <cuda_runtime.h>
#include <math.h>
#include <stdint.h>

// Problem constants
#define BB 4
#define SS 2048
#define HH 16
#define DH 64
#define DD 1024            // H*DH
#define ROWS (BB*SS)       // 8192
#define N_QKV (3*DD)       // 3072
#define FF_IN 4096
#define FF_HID 2048

// Scratch (device globals; no allocation)
__device__ float g_aq  [(size_t)ROWS * DD];      // tf32-rounded q input
__device__ float g_q   [(size_t)ROWS * DD];      // [B*H, S, 64] tf32, pre-scaled 0.125
__device__ float g_k   [(size_t)ROWS * DD];      // [B*H, S, 64] tf32
__device__ float g_vT  [(size_t)ROWS * DD];      // [B*H, 64, S] tf32
__device__ float g_attn[(size_t)ROWS * DD];      // [B*S, 1024]
__device__ float g_ln  [(size_t)ROWS * DD];      // LN out (fp32, residual)
__device__ float g_lnr [(size_t)ROWS * DD];      // LN out tf32-rounded (GEMM A)
__device__ float g_gate[(size_t)ROWS * FF_HID];  // [B*S, 2048] tf32-rounded
__device__ float g_wqkvT[(size_t)N_QKV * DD];    // [3072, 1024]
__device__ float g_w1T  [(size_t)FF_IN * DD];    // [4096, 1024] x/gate interleaved
__device__ float g_w2T  [(size_t)DD * FF_HID];   // [1024, 2048]
__device__ float g_pb1  [FF_IN];                 // permuted b1

// ---------------------------------------------------------------------------
// helpers
// ---------------------------------------------------------------------------
__device__ __forceinline__ float tf32r(float x) {
    float o; asm("cvt.rna.tf32.f32 %0, %1;" : "=f"(o) : "f"(x)); return o;
}
__device__ __forceinline__ uint32_t smem_u32(const void* p) {
    uint32_t a;
    asm("{ .reg .u64 t; cvta.to.shared.u64 t, %1; cvt.u32.u64 %0, t; }" : "=r"(a) : "l"(p));
    return a;
}
__device__ __forceinline__ void cpasync16(uint32_t dst, const void* src) {
    asm volatile("cp.async.cg.shared.global [%0], [%1], 16;" :: "r"(dst), "l"(src) : "memory");
}
__device__ __forceinline__ void cp_commit() {
    asm volatile("cp.async.commit_group;" ::: "memory");
}
__device__ __forceinline__ void cp_wait1() {
    asm volatile("cp.async.wait_group 1;" ::: "memory");
}
__device__ __forceinline__ void cp_wait0() {
    asm volatile("cp.async.wait_group 0;" ::: "memory");
}
// NOTE: non-volatile — pure register op, lets the compiler interleave with LDSM
__device__ __forceinline__ void mma_tf32(float* c, const uint32_t* a, const uint32_t* b) {
    asm("mma.sync.aligned.m16n8k8.row.col.f32.tf32.tf32.f32 "
        "{%0,%1,%2,%3}, {%4,%5,%6,%7}, {%8,%9}, {%0,%1,%2,%3};"
        : "+f"(c[0]), "+f"(c[1]), "+f"(c[2]), "+f"(c[3])
        : "r"(a[0]), "r"(a[1]), "r"(a[2]), "r"(a[3]), "r"(b[0]), "r"(b[1]));
}
__device__ __forceinline__ void ldsm4(uint32_t* r, uint32_t addr) {
    asm volatile("ldmatrix.sync.aligned.m8n8.x4.shared.b16 {%0,%1,%2,%3}, [%4];"
        : "=r"(r[0]), "=r"(r[1]), "=r"(r[2]), "=r"(r[3]) : "r"(addr));
}

// ---------------------------------------------------------------------------
// tf32 mma.sync GEMM: C[M,N] = A[M,K] @ Bt[N,K]^T + bias (+ res)
// MODE 0: plain (+res).   MODE 1: fused SwiGLU (interleaved x/gate cols).
// MODE 2: fused QKV epilogue (l2norm+scale+RoPE for q/k, transposed V store).
// 3-stage cp.async pipeline, 1 barrier/iter, ldmatrix loads, ldsm/mma interleave.
// ---------------------------------------------------------------------------
#define GBM 128
#define GBN 128
#define GBK 32
#define APAD 36
#define STAGE_F (2 * 128 * APAD)   // floats per stage (A+B)
#define NSTAGE 3

template<int MODE>
__global__ __launch_bounds__(256) void gemm_mma_kernel(
    const float* __restrict__ A, const float* __restrict__ Bt,
    const float* __restrict__ bias, const float* __restrict__ res,
    const float* __restrict__ qsc, const float* __restrict__ ksc,
    float* __restrict__ C, int N, int K)
{
    extern __shared__ float sm[];
    const int tid = threadIdx.x;
    const int wid = tid >> 5, lane = tid & 31;
    const int g = lane >> 2, tg = lane & 3;
    const int warp_m = wid & 3, warp_n = wid >> 2;
    const int m0 = blockIdx.y * GBM, n0 = blockIdx.x * GBN;
    const uint32_t smbase = smem_u32(sm);

    float acc[2][8][4] = {};

    const int NIT = K >> 5;

    auto load_stage = [&](int it, int s) {
        const int k0 = it * GBK;
        const uint32_t aB = smbase + (uint32_t)s * STAGE_F * 4;
        const uint32_t bB = aB + 128 * APAD * 4;
#pragma unroll
        for (int i = 0; i < 4; i++) {
            const int idx = tid + 256 * i;
            const int row = idx >> 3, c4 = (idx & 7) * 4;
            cpasync16(aB + (uint32_t)(row * APAD + c4) * 4,
                      A  + (size_t)(m0 + row) * K + k0 + c4);
            cpasync16(bB + (uint32_t)(row * APAD + c4) * 4,
                      Bt + (size_t)(n0 + row) * K + k0 + c4);
        }
        cp_commit();
    };

    // ldmatrix lane-address components (byte offsets within stage)
    const int lane15 = lane & 15;
    const uint32_t aoff = ((lane >> 4) & 1) * 16;
    const int brow  = lane & 7;
    const int bsel  = (lane >> 4) & 1;
    const uint32_t boff = ((lane >> 3) & 1) * 16;

    const uint32_t aAdr0 = (uint32_t)((warp_m * 32 + 0  + lane15) * APAD) * 4 + aoff;
    const uint32_t aAdr1 = (uint32_t)((warp_m * 32 + 16 + lane15) * APAD) * 4 + aoff;
    uint32_t bAdr[4];
#pragma unroll
    for (int p = 0; p < 4; p++)
        bAdr[p] = (uint32_t)(128 * APAD + (warp_n * 64 + (2 * p + bsel) * 8 + brow) * APAD) * 4 + boff;

    load_stage(0, 0);
    load_stage(1, 1);

    for (int it = 0; it < NIT; it++) {
        const int s = it % NSTAGE;
        if (it + 1 < NIT) cp_wait1(); else cp_wait0();
        __syncthreads();
        if (it + 2 < NIT) load_stage(it + 2, (it + 2) % NSTAGE);

        const uint32_t stg = smbase + (uint32_t)s * STAGE_F * 4;

#pragma unroll
        for (int kt = 0; kt < 4; kt++) {
            const uint32_t ko = kt * 32;   // 8 floats = 32 bytes
            uint32_t a[2][4], bb[4][4];
            ldsm4(a[0], stg + aAdr0 + ko);
            ldsm4(a[1], stg + aAdr1 + ko);
            ldsm4(bb[0], stg + bAdr[0] + ko);
            ldsm4(bb[1], stg + bAdr[1] + ko);
#pragma unroll
            for (int mi = 0; mi < 2; mi++)
#pragma unroll
                for (int ni = 0; ni < 4; ni++)
                    mma_tf32(acc[mi][ni], a[mi], &bb[ni >> 1][(ni & 1) * 2]);
            ldsm4(bb[2], stg + bAdr[2] + ko);
            ldsm4(bb[3], stg + bAdr[3] + ko);
#pragma unroll
            for (int mi = 0; mi < 2; mi++)
#pragma unroll
                for (int ni = 4; ni < 8; ni++)
                    mma_tf32(acc[mi][ni], a[mi], &bb[ni >> 1][(ni & 1) * 2]);
        }
    }

    if (MODE == 2) {
        // --- fused QKV epilogue ---
        const int segcol = n0 + warp_n * 64;
        const int h   = segcol / 192;
        const int seg = (segcol >> 6) % 3;            // 0=q, 1=k, 2=v
#pragma unroll
        for (int mi = 0; mi < 2; mi++) {
#pragma unroll
            for (int hf = 0; hf < 2; hf++) {
                const int row  = m0 + warp_m * 32 + mi * 16 + g + hf * 8;
                const int b    = row >> 11;
                const int spos = row & (SS - 1);
                float v[8][2];
#pragma unroll
                for (int ni = 0; ni < 8; ni++) {
#pragma unroll
                    for (int c = 0; c < 2; c++)
                        v[ni][c] = acc[mi][ni][hf * 2 + c] + bias[segcol + ni * 8 + tg * 2 + c];
                }
                if (seg == 2) {
                    float* dst = g_vT + ((size_t)(b * HH + h) * DH) * SS + spos;
#pragma unroll
                    for (int ni = 0; ni < 8; ni++) {
#pragma unroll
                        for (int c = 0; c < 2; c++)
                            dst[(size_t)(ni * 8 + tg * 2 + c) * SS] = tf32r(v[ni][c]);
                    }
                } else {
                    float ssum = 0.0f;
#pragma unroll
                    for (int ni = 0; ni < 8; ni++)
                        ssum += v[ni][0] * v[ni][0] + v[ni][1] * v[ni][1];
                    ssum += __shfl_xor_sync(0xffffffffu, ssum, 1);
                    ssum += __shfl_xor_sync(0xffffffffu, ssum, 2);
                    const float inv = 1.0f / fmaxf(sqrtf(ssum), 1e-12f);
                    const float* sv = seg ? ksc : qsc;
#pragma unroll
                    for (int ni = 0; ni < 8; ni++) {
#pragma unroll
                        for (int c = 0; c < 2; c++)
                            v[ni][c] *= inv * sv[ni * 8 + tg * 2 + c];
                    }
                    const float power = ((float)spos - 1024.0f) * (1.0f / 512.0f);
                    float outv[8][2];
#pragma unroll
                    for (int ni = 0; ni < 4; ni++) {
#pragma unroll
                        for (int c = 0; c < 2; c++) {
                            const int j = ni * 8 + tg * 2 + c;
                            const float invf = __expf(-(float)j * 0.28782313662425574f);
                            float sn, cs;
                            __sincosf((float)spos * invf, &sn, &cs);
                            float sc = __powf((2.0f * j + 25.6f) * (1.0f / 89.6f), power);
                            if (seg == 1) sc = 1.0f / sc;
                            outv[ni][c]     = (v[ni][c] * cs - v[ni + 4][c] * sn) * sc;
                            outv[ni + 4][c] = (v[ni + 4][c] * cs + v[ni][c] * sn) * sc;
                        }
                    }
                    const float mul = seg ? 1.0f : 0.125f;
                    float* dst = (seg ? g_k : g_q) + ((size_t)((b * HH + h) * SS + spos)) * DH;
#pragma unroll
                    for (int ni = 0; ni < 8; ni++) {
                        float2 w;
                        w.x = tf32r(outv[ni][0] * mul);
                        w.y = tf32r(outv[ni][1] * mul);
                        *(float2*)(dst + ni * 8 + tg * 2) = w;
                    }
                }
            }
        }
    } else if (MODE == 1) {
        const int NH = N >> 1;
#pragma unroll
        for (int mi = 0; mi < 2; mi++) {
            const int row0 = m0 + warp_m * 32 + mi * 16 + g;
#pragma unroll
            for (int ni = 0; ni < 8; ni++) {
                const int col = n0 + warp_n * 64 + ni * 8 + tg * 2;
                const float2 bv = *(const float2*)(bias + col);
                const float x0 = acc[mi][ni][0] + bv.x;
                const float g0 = acc[mi][ni][1] + bv.y;
                const float x1 = acc[mi][ni][2] + bv.x;
                const float g1 = acc[mi][ni][3] + bv.y;
                const float o0 = tf32r(x0 * g0 * __frcp_rn(1.0f + __expf(-g0)));
                const float o1 = tf32r(x1 * g1 * __frcp_rn(1.0f + __expf(-g1)));
                const float p0 = __shfl_xor_sync(0xffffffffu, o0, 1);
                const float p1 = __shfl_xor_sync(0xffffffffu, o1, 1);
                const int cp = col >> 1;
                if ((tg & 1) == 0) {
                    *(float2*)(C + (size_t)row0 * NH + cp) = make_float2(o0, p0);
                } else {
                    *(float2*)(C + (size_t)(row0 + 8) * NH + cp - 1) = make_float2(p1, o1);
                }
            }
        }
    } else {
#pragma unroll
        for (int mi = 0; mi < 2; mi++) {
            const int row0 = m0 + warp_m * 32 + mi * 16 + g;
#pragma unroll
            for (int ni = 0; ni < 8; ni++) {
                const int col = n0 + warp_n * 64 + ni * 8 + tg * 2;
                const float2 bv = *(const float2*)(bias + col);
                float2 o0, o1;
                o0.x = acc[mi][ni][0] + bv.x;
                o0.y = acc[mi][ni][1] + bv.y;
                o1.x = acc[mi][ni][2] + bv.x;
                o1.y = acc[mi][ni][3] + bv.y;
                if (res) {
                    const float2 r0 = *(const float2*)(res + (size_t)row0 * N + col);
                    const float2 r1 = *(const float2*)(res + (size_t)(row0 + 8) * N + col);
                    o0.x += r0.x; o0.y += r0.y; o1.x += r1.x; o1.y += r1.y;
                }
                *(float2*)(C + (size_t)row0 * N + col) = o0;
                *(float2*)(C + (size_t)(row0 + 8) * N + col) = o1;
            }
        }
    }
}

// ---------------------------------------------------------------------------
// Transpose + tf32-round: out[c*R + r] = rnd(in[r*Cc + c])
// ---------------------------------------------------------------------------
template<int PERM>
__global__ __launch_bounds__(256) void transpose_round_kernel(
    const float* __restrict__ in, float* __restrict__ out, int R, int Cc)
{
    __shared__ float t[32][33];
    const int bx = blockIdx.x, by = blockIdx.y;
    const int tx = threadIdx.x, ty = threadIdx.y;
#pragma unroll
    for (int i = 0; i < 32; i += 8)
        t[ty + i][tx] = in[(size_t)(by * 32 + ty + i) * Cc + bx * 32 + tx];
    __syncthreads();
#pragma unroll
    for (int i = 0; i < 32; i += 8) {
        int r = bx * 32 + ty + i;
        if (PERM) r = (r < 2048) ? (2 * r) : (2 * (r - 2048) + 1);
        out[(size_t)r * R + by * 32 + tx] = tf32r(t[tx][ty + i]);
    }
}

// permute b1: out[2c]=b1[c], out[2c+1]=b1[2048+c]
__global__ __launch_bounds__(256) void permute_b1_kernel(const float* __restrict__ b1)
{
    const int c = blockIdx.x * 256 + threadIdx.x;
    g_pb1[2 * c]     = b1[c];
    g_pb1[2 * c + 1] = b1[FF_HID + c];
}

__global__ __launch_bounds__(256) void round_copy_kernel(
    const float* __restrict__ in, float* __restrict__ out)
{
    const int i = blockIdx.x * 256 + threadIdx.x;
    float4 v = ((const float4*)in)[i];
    v.x = tf32r(v.x); v.y = tf32r(v.y); v.z = tf32r(v.z); v.w = tf32r(v.w);
    ((float4*)out)[i] = v;
}

// ---------------------------------------------------------------------------
// Flash attention via mma.sync tf32 + ldmatrix fragment loads.
// ---------------------------------------------------------------------------
#define ATT_PAD 68
#define ATT_QF   (128 * ATT_PAD)           // Q floats
#define ATT_STF  (2 * 64 * ATT_PAD)        // per-stage floats (K + V^T)

__global__ __launch_bounds__(128) void attn_mma_kernel()
{
    extern __shared__ float sm[];
    float* Qs = sm;

    const int bh = blockIdx.x;
    const int q0 = blockIdx.y * 128;
    const int tid = threadIdx.x, wid = tid >> 5, lane = tid & 31;
    const int g = lane >> 2, tg = lane & 3;
    const uint32_t smbase = smem_u32(sm);

    const float* Q  = g_q + ((size_t)bh * SS + q0) * DH;
    const float* K  = g_k + (size_t)bh * SS * DH;
    const float* Vt = g_vT + (size_t)bh * DH * SS;

    for (int i = tid; i < 128 * 16; i += 128) {
        const int r = i >> 4, c4 = (i & 15) * 4;
        *(float4*)(&Qs[r * ATT_PAD + c4]) = *(const float4*)(Q + r * DH + c4);
    }

    auto load_kv = [&](int t, int s) {
        const uint32_t kB = smbase + (ATT_QF + s * ATT_STF) * 4;
        const uint32_t vB = kB + 64 * ATT_PAD * 4;
        const float* Kg = K + (size_t)t * 64 * DH;
#pragma unroll
        for (int i = 0; i < 8; i++) {
            const int idx = tid + 128 * i;
            const int r = idx >> 4, c4 = (idx & 15) * 4;
            cpasync16(kB + (uint32_t)(r * ATT_PAD + c4) * 4, Kg + r * DH + c4);
            cpasync16(vB + (uint32_t)(r * ATT_PAD + c4) * 4, Vt + (size_t)r * SS + t * 64 + c4);
        }
        cp_commit();
    };

    // ldmatrix address components (same validated mapping as GEMM)
    const int lane15 = lane & 15;
    const uint32_t aoff = ((lane >> 4) & 1) * 16;
    const int brow  = lane & 7;
    const int bsel  = (lane >> 4) & 1;
    const uint32_t boff = ((lane >> 3) & 1) * 16;

    const uint32_t qAdr0 = (uint32_t)((wid * 32 + 0  + lane15) * ATT_PAD) * 4 + aoff;
    const uint32_t qAdr1 = (uint32_t)((wid * 32 + 16 + lane15) * ATT_PAD) * 4 + aoff;
    uint32_t kvAdr[4];
#pragma unroll
    for (int p = 0; p < 4; p++)
        kvAdr[p] = (uint32_t)(((2 * p + bsel) * 8 + brow) * ATT_PAD) * 4 + boff;

    load_kv(0, 0);

    float acc[2][8][4] = {};
    float mrow[4] = {-1e30f, -1e30f, -1e30f, -1e30f};
    float lrow[4] = {};

    const int NT = SS / 64;
    for (int t = 0; t < NT; t++) {
        const int s = t & 1;
        if (t + 1 < NT) load_kv(t + 1, s ^ 1);
        if (t + 1 < NT) cp_wait1(); else cp_wait0();
        __syncthreads();

        const uint32_t ksB = smbase + (ATT_QF + s * ATT_STF) * 4;
        const uint32_t vsB = ksB + 64 * ATT_PAD * 4;

        // --- S = Q @ K^T ---
        float sc[2][8][4] = {};
#pragma unroll
        for (int kt = 0; kt < 8; kt++) {
            const uint32_t ko = kt * 32;
            uint32_t aq[2][4], bb[4][4];
            ldsm4(aq[0], smbase + qAdr0 + ko);
            ldsm4(aq[1], smbase + qAdr1 + ko);
            ldsm4(bb[0], ksB + kvAdr[0] + ko);
            ldsm4(bb[1], ksB + kvAdr[1] + ko);
#pragma unroll
            for (int mi = 0; mi < 2; mi++)
#pragma unroll
                for (int ni = 0; ni < 4; ni++)
                    mma_tf32(sc[mi][ni], aq[mi], &bb[ni >> 1][(ni & 1) * 2]);
            ldsm4(bb[2], ksB + kvAdr[2] + ko);
            ldsm4(bb[3], ksB + kvAdr[3] + ko);
#pragma unroll
            for (int mi = 0; mi < 2; mi++)
#pragma unroll
                for (int ni = 4; ni < 8; ni++)
                    mma_tf32(sc[mi][ni], aq[mi], &bb[ni >> 1][(ni & 1) * 2]);
        }

        // --- online softmax ---
#pragma unroll
        for (int mi = 0; mi < 2; mi++) {
#pragma unroll
            for (int hf = 0; hf < 2; hf++) {
                const int r = mi * 2 + hf;
                float mx = -1e30f;
#pragma unroll
                for (int ni = 0; ni < 8; ni++)
                    mx = fmaxf(mx, fmaxf(sc[mi][ni][hf * 2], sc[mi][ni][hf * 2 + 1]));
                mx = fmaxf(mx, __shfl_xor_sync(0xffffffffu, mx, 1));
                mx = fmaxf(mx, __shfl_xor_sync(0xffffffffu, mx, 2));
                const float newm = fmaxf(mrow[r], mx);
                const float corr = __expf(mrow[r] - newm);
                mrow[r] = newm;
                float sum = 0.0f;
#pragma unroll
                for (int ni = 0; ni < 8; ni++) {
                    const float p0 = __expf(sc[mi][ni][hf * 2]     - newm);
                    const float p1 = __expf(sc[mi][ni][hf * 2 + 1] - newm);
                    sum += p0 + p1;
                    sc[mi][ni][hf * 2]     = p0;
                    sc[mi][ni][hf * 2 + 1] = p1;
                }
                sum += __shfl_xor_sync(0xffffffffu, sum, 1);
                sum += __shfl_xor_sync(0xffffffffu, sum, 2);
                lrow[r] = lrow[r] * corr + sum;
#pragma unroll
                for (int nd = 0; nd < 8; nd++) {
                    acc[mi][nd][hf * 2]     *= corr;
                    acc[mi][nd][hf * 2 + 1] *= corr;
                }
            }
        }

        // --- O += P @ V (P frag conversion via shfl) ---
        const int src0 = g * 4 + (tg >> 1);
        const int src1 = src0 + 2;
        const bool odd = tg & 1;
#pragma unroll
        for (int kt = 0; kt < 8; kt++) {
            const uint32_t ko = kt * 32;
            uint32_t ap[2][4];
#pragma unroll
            for (int mi = 0; mi < 2; mi++) {
                const float c0 = sc[mi][kt][0], c1 = sc[mi][kt][1];
                const float c2 = sc[mi][kt][2], c3 = sc[mi][kt][3];
                const float v00 = __shfl_sync(0xffffffffu, c0, src0);
                const float v01 = __shfl_sync(0xffffffffu, c1, src0);
                const float v10 = __shfl_sync(0xffffffffu, c0, src1);
                const float v11 = __shfl_sync(0xffffffffu, c1, src1);
                const float v20 = __shfl_sync(0xffffffffu, c2, src0);
                const float v21 = __shfl_sync(0xffffffffu, c3, src0);
                const float v30 = __shfl_sync(0xffffffffu, c2, src1);
                const float v31 = __shfl_sync(0xffffffffu, c3, src1);
                ap[mi][0] = __float_as_uint(tf32r(odd ? v01 : v00));
                ap[mi][1] = __float_as_uint(tf32r(odd ? v21 : v20));
                ap[mi][2] = __float_as_uint(tf32r(odd ? v11 : v10));
                ap[mi][3] = __float_as_uint(tf32r(odd ? v31 : v30));
            }
            uint32_t bb[4][4];
            ldsm4(bb[0], vsB + kvAdr[0] + ko);
            ldsm4(bb[1], vsB + kvAdr[1] + ko);
#pragma unroll
            for (int mi = 0; mi < 2; mi++)
#pragma unroll
                for (int nd = 0; nd < 4; nd++)
                    mma_tf32(acc[mi][nd], ap[mi], &bb[nd >> 1][(nd & 1) * 2]);
            ldsm4(bb[2], vsB + kvAdr[2] + ko);
            ldsm4(bb[3], vsB + kvAdr[3] + ko);
#pragma unroll
            for (int mi = 0; mi < 2; mi++)
#pragma unroll
                for (int nd = 4; nd < 8; nd++)
                    mma_tf32(acc[mi][nd], ap[mi], &bb[nd >> 1][(nd & 1) * 2]);
        }
        __syncthreads();
    }

    const int b = bh >> 4, h = bh & 15;
#pragma unroll
    for (int mi = 0; mi < 2; mi++) {
        const int row0 = q0 + wid * 32 + mi * 16 + g;
        const float inv0 = 1.0f / lrow[mi * 2 + 0];
        const float inv1 = 1.0f / lrow[mi * 2 + 1];
#pragma unroll
        for (int nd = 0; nd < 8; nd++) {
            const int col = h * 64 + nd * 8 + tg * 2;
            float2 o0, o1;
            o0.x = acc[mi][nd][0] * inv0; o0.y = acc[mi][nd][1] * inv0;
            o1.x = acc[mi][nd][2] * inv1; o1.y = acc[mi][nd][3] * inv1;
            *(float2*)(g_attn + ((size_t)(b * SS + row0)) * DD + col) = o0;
            *(float2*)(g_attn + ((size_t)(b * SS + row0 + 8)) * DD + col) = o1;
        }
    }
}

// ---------------------------------------------------------------------------
// LayerNorm; writes fp32 g_ln (residual) and tf32-rounded g_lnr (GEMM A)
// ---------------------------------------------------------------------------
__global__ __launch_bounds__(256) void ln_kernel(
    const float* __restrict__ gw, const float* __restrict__ bw)
{
    __shared__ float red[64];
    const int r = blockIdx.x;
    const int t = threadIdx.x;

    const float4 x = ((const float4*)(g_attn + (size_t)r * DD))[t];
    float s  = x.x + x.y + x.z + x.w;
    float ss = x.x*x.x + x.y*x.y + x.z*x.z + x.w*x.w;
#pragma unroll
    for (int o = 16; o > 0; o >>= 1) {
        s  += __shfl_xor_sync(0xffffffffu, s,  o);
        ss += __shfl_xor_sync(0xffffffffu, ss, o);
    }
    if ((t & 31) == 0) { red[t >> 5] = s; red[32 + (t >> 5)] = ss; }
    __syncthreads();
    if (t == 0) {
        float S = 0, SSum = 0;
#pragma unroll
        for (int i = 0; i < 8; i++) { S += red[i]; SSum += red[32 + i]; }
        red[0] = S; red[32] = SSum;
    }
    __syncthreads();
    const float mu  = red[0]  * (1.0f / DD);
    const float var = red[32] * (1.0f / DD) - mu * mu;
    const float inv = rsqrtf(var + 1e-5f);

    const int c = t * 4;
    float4 o;
    o.x = (x.x - mu) * inv * gw[c + 0] + bw[c + 0];
    o.y = (x.y - mu) * inv * gw[c + 1] + bw[c + 1];
    o.z = (x.z - mu) * inv * gw[c + 2] + bw[c + 2];
    o.w = (x.w - mu) * inv * gw[c + 3] + bw[c + 3];
    ((float4*)(g_ln + (size_t)r * DD))[t] = o;
    float4 orr;
    orr.x = tf32r(o.x); orr.y = tf32r(o.y); orr.z = tf32r(o.z); orr.w = tf32r(o.w);
    ((float4*)(g_lnr + (size_t)r * DD))[t] = orr;
}

// ---------------------------------------------------------------------------
extern "C" void kernel_launch(void* const* d_in, const int* in_sizes, int n_in,
                              void* d_out, int out_size)
{
    const float* q       = (const float*)d_in[0];
    const float* Wqkv    = (const float*)d_in[3];
    const float* bqkv    = (const float*)d_in[4];
    const float* q_scale = (const float*)d_in[5];
    const float* k_scale = (const float*)d_in[6];
    const float* ln_g    = (const float*)d_in[7];
    const float* ln_b    = (const float*)d_in[8];
    const float* W1      = (const float*)d_in[9];
    const float* b1      = (const float*)d_in[10];
    const float* W2      = (const float*)d_in[11];
    const float* b2      = (const float*)d_in[12];
    float* out = (float*)d_out;

    float *p_aq, *p_ln, *p_lnr, *p_gate, *p_wqkvT, *p_w1T, *p_w2T, *p_pb1;
    cudaGetSymbolAddress((void**)&p_aq,    g_aq);
    cudaGetSymbolAddress((void**)&p_ln,    g_ln);
    cudaGetSymbolAddress((void**)&p_lnr,   g_lnr);
    cudaGetSymbolAddress((void**)&p_gate,  g_gate);
    cudaGetSymbolAddress((void**)&p_wqkvT, g_wqkvT);
    cudaGetSymbolAddress((void**)&p_w1T,   g_w1T);
    cudaGetSymbolAddress((void**)&p_w2T,   g_w2T);
    cudaGetSymbolAddress((void**)&p_pb1,   g_pb1);

    const int GSMEM = STAGE_F * NSTAGE * 4;               // 110592 bytes
    const int ASMEM = (ATT_QF + 2 * ATT_STF) * 4;         // 104448 bytes
    cudaFuncSetAttribute(gemm_mma_kernel<0>, cudaFuncAttributeMaxDynamicSharedMemorySize, GSMEM);
    cudaFuncSetAttribute(gemm_mma_kernel<1>, cudaFuncAttributeMaxDynamicSharedMemorySize, GSMEM);
    cudaFuncSetAttribute(gemm_mma_kernel<2>, cudaFuncAttributeMaxDynamicSharedMemorySize, GSMEM);
    cudaFuncSetAttribute(attn_mma_kernel, cudaFuncAttributeMaxDynamicSharedMemorySize, ASMEM);

    // 0-2: prep (QKV GEMM stays at launch index 3 -> ncu capture slot)
    transpose_round_kernel<0><<<dim3(N_QKV / 32, DD / 32), dim3(32, 8)>>>(Wqkv, p_wqkvT, DD, N_QKV);
    round_copy_kernel<<<ROWS * DD / 4 / 256, 256>>>(q, p_aq);
    transpose_round_kernel<1><<<dim3(FF_IN / 32, DD / 32), dim3(32, 8)>>>(W1, p_w1T, DD, FF_IN);

    // 3: QKV projection + fused l2norm/scale/RoPE/V-transpose epilogue
    gemm_mma_kernel<2><<<dim3(N_QKV / GBN, ROWS / GBM), 256, GSMEM>>>(
        p_aq, p_wqkvT, bqkv, nullptr, q_scale, k_scale, nullptr, N_QKV, DD);

    // 4-5: remaining prep
    transpose_round_kernel<0><<<dim3(DD / 32, FF_HID / 32), dim3(32, 8)>>>(W2, p_w2T, FF_HID, DD);
    permute_b1_kernel<<<FF_HID / 256, 256>>>(b1);

    // 6: attention (tensor cores)
    attn_mma_kernel<<<dim3(BB * HH, SS / 128), 128, ASMEM>>>();

    // 7: LayerNorm
    ln_kernel<<<ROWS, 256>>>(ln_g, ln_b);

    // 8: FF1 + fused SwiGLU, writes g_gate
    gemm_mma_kernel<1><<<dim3(FF_IN / GBN, ROWS / GBM), 256, GSMEM>>>(
        p_lnr, p_w1T, p_pb1, nullptr, nullptr, nullptr, p_gate, FF_IN, DD);

    // 9: FF2 + bias + residual(ln)
    gemm_mma_kernel<0><<<dim3(DD / GBN, ROWS / GBM), 256, GSMEM>>>(
        p_gate, p_w2T, b2, p_ln, nullptr, nullptr, out, DD, FF_HID);
}